// round 7
// baseline (speedup 1.0000x reference)
#include <cuda_runtime.h>
#include <cstdint>

constexpr int C = 32, K1C = 128, K2C = 512, FCC = 256;
constexpr int MAXN = 524288, MAXB = 16, SCH = 16;
constexpr float EPS_BN = 1e-5f;

__device__ float g_h  [(size_t)MAXN * K1C];           // h_pre fp32 [N][128]
__device__ float g_p1s [(MAXN / 256) * K1C];
__device__ float g_p1q [(MAXN / 256) * K1C];
__device__ float g_p2s [(size_t)K2C * (MAXN / 128)];  // [ch][blk]
__device__ float g_p2q [(size_t)K2C * (MAXN / 128)];
__device__ float g_a1[K1C], g_bb1[K1C], g_a2[K2C], g_bb2[K2C];
__device__ float g_ppool[(size_t)MAXB * SCH * K2C * C];
__device__ float g_pgp  [(size_t)MAXB * SCH * K2C];
__device__ float g_pooled[(size_t)MAXB * K2C * C];
__device__ float g_resb [MAXB * FCC];

__device__ __forceinline__ float tf32r(float v) {
    float o; asm("cvt.rna.tf32.f32 %0, %1;" : "=f"(o) : "f"(v)); return o;
}
__device__ __forceinline__ void mma8(float* d, const uint32_t* a, const uint32_t* b) {
    asm volatile(
        "mma.sync.aligned.m16n8k8.row.col.f32.tf32.tf32.f32 "
        "{%0,%1,%2,%3}, {%4,%5,%6,%7}, {%8,%9}, {%0,%1,%2,%3};"
        : "+f"(d[0]), "+f"(d[1]), "+f"(d[2]), "+f"(d[3])
        : "r"(a[0]), "r"(a[1]), "r"(a[2]), "r"(a[3]), "r"(b[0]), "r"(b[1]));
}

// ---------------- GEMM1 (fp32 SIMT) ----------------
__global__ void __launch_bounds__(128) k_gemm1(const float* __restrict__ x,
                                               const float* __restrict__ w1,
                                               const float* __restrict__ b1) {
    __shared__ float sx[256 * C];
    const int k = threadIdx.x, p0 = blockIdx.x * 256;
    const float4* xg = reinterpret_cast<const float4*>(x) + (size_t)p0 * (C / 4);
    float4* sx4 = reinterpret_cast<float4*>(sx);
#pragma unroll
    for (int i = 0; i < 16; i++) sx4[threadIdx.x + i * 128] = xg[threadIdx.x + i * 128];
    float w[C];
#pragma unroll
    for (int c = 0; c < C; c++) w[c] = __ldg(&w1[k * C + c]);
    const float bias = __ldg(&b1[k]);
    __syncthreads();
    float s = 0.f, q = 0.f;
    float* hp = g_h + (size_t)p0 * K1C + k;
    for (int p = 0; p < 256; p++) {
        const float4* xr = reinterpret_cast<const float4*>(sx + p * C);
        float acc = bias;
#pragma unroll
        for (int c4 = 0; c4 < 8; c4++) {
            float4 v = xr[c4];
            acc = fmaf(w[c4 * 4 + 0], v.x, acc);
            acc = fmaf(w[c4 * 4 + 1], v.y, acc);
            acc = fmaf(w[c4 * 4 + 2], v.z, acc);
            acc = fmaf(w[c4 * 4 + 3], v.w, acc);
        }
        hp[(size_t)p * K1C] = acc;
        s += acc; q = fmaf(acc, acc, q);
    }
    g_p1s[blockIdx.x * K1C + k] = s;
    g_p1q[blockIdx.x * K1C + k] = q;
}

// ---------------- BN finalize ----------------
__global__ void k_fin1(const float* __restrict__ g, const float* __restrict__ be,
                       int nblk, float invN) {
    const int ch = blockIdx.x;
    __shared__ float rs[256], rq[256];
    float s = 0.f, q = 0.f;
    for (int i = threadIdx.x; i < nblk; i += 256) {
        s += g_p1s[i * K1C + ch]; q += g_p1q[i * K1C + ch];
    }
    rs[threadIdx.x] = s; rq[threadIdx.x] = q; __syncthreads();
    for (int o = 128; o > 0; o >>= 1) {
        if (threadIdx.x < o) { rs[threadIdx.x] += rs[threadIdx.x + o]; rq[threadIdx.x] += rq[threadIdx.x + o]; }
        __syncthreads();
    }
    if (threadIdx.x == 0) {
        float mu = rs[0] * invN, var = rq[0] * invN - mu * mu;
        float a = g[ch] * rsqrtf(var + EPS_BN);
        g_a1[ch] = a; g_bb1[ch] = be[ch] - mu * a;
    }
}
__global__ void k_fin2(const float* __restrict__ g, const float* __restrict__ be,
                       int nblk, float invN) {
    const int ch = blockIdx.x;
    __shared__ float rs[256], rq[256];
    float s = 0.f, q = 0.f;
    const float* ps = g_p2s + (size_t)ch * nblk;
    const float* pq = g_p2q + (size_t)ch * nblk;
    for (int i = threadIdx.x; i < nblk; i += 256) { s += ps[i]; q += pq[i]; }
    rs[threadIdx.x] = s; rq[threadIdx.x] = q; __syncthreads();
    for (int o = 128; o > 0; o >>= 1) {
        if (threadIdx.x < o) { rs[threadIdx.x] += rs[threadIdx.x + o]; rq[threadIdx.x] += rq[threadIdx.x + o]; }
        __syncthreads();
    }
    if (threadIdx.x == 0) {
        float mu = rs[0] * invN, var = rq[0] * invN - mu * mu;
        float a = g[ch] * rsqrtf(var + EPS_BN);
        g_a2[ch] = a; g_bb2[ch] = be[ch] - mu * a;
    }
}

// ---------------- Pass 1: GEMM2 stats only (no att store) ----------------
constexpr int S2_OFF_BS = 16384, S2_OFF_SA1 = 24576, S2_OFF_SB1 = 24704;
constexpr int S2_OFF_SB2 = 24832, S2_OFF_PS = 25344, S2_OFF_PQ = 25600;
constexpr int S2_SMEM_FLOATS = 25856;

__global__ void __launch_bounds__(256, 2) k_stat2(const float* __restrict__ w2,
                                                  const float* __restrict__ b2,
                                                  int nblk) {
    extern __shared__ float sm[];
    float* As = sm;
    float* Bs = sm + S2_OFF_BS;
    float* sA1 = sm + S2_OFF_SA1;
    float* sB1 = sm + S2_OFF_SB1;
    float* sb2 = sm + S2_OFF_SB2;
    float* ps  = sm + S2_OFF_PS;
    float* pq  = sm + S2_OFF_PQ;
    const int tid = threadIdx.x, lane = tid & 31, warp = tid >> 5;
    const int wm = warp >> 1, wn = warp & 1;
    const int gid = lane >> 2, tig = lane & 3;
    const int row0 = blockIdx.x * 128;

    if (tid < 128) { sA1[tid] = g_a1[tid]; sB1[tid] = g_bb1[tid]; }
    sb2[tid] = __ldg(&b2[tid]); sb2[tid + 256] = __ldg(&b2[tid + 256]);
    __syncthreads();

#pragma unroll
    for (int i = 0; i < 16; i++) {
        int q = tid + i * 256;
        int r = q >> 5, k4 = (q & 31) * 4;
        float4 v = *reinterpret_cast<const float4*>(&g_h[(size_t)(row0 + r) * K1C + k4]);
        float vv[4];
        vv[0] = tf32r(fmaxf(fmaf(sA1[k4 + 0], v.x, sB1[k4 + 0]), 0.f));
        vv[1] = tf32r(fmaxf(fmaf(sA1[k4 + 1], v.y, sB1[k4 + 1]), 0.f));
        vv[2] = tf32r(fmaxf(fmaf(sA1[k4 + 2], v.z, sB1[k4 + 2]), 0.f));
        vv[3] = tf32r(fmaxf(fmaf(sA1[k4 + 3], v.w, sB1[k4 + 3]), 0.f));
        int mt = r >> 4, rr = r & 15;
        int kt = k4 >> 3, reg = (rr >> 3) + ((k4 & 7) >> 2) * 2;
        int slotb = (rr & 7) * 4;
        float* base = As + (mt * 16 + kt) * 128;
#pragma unroll
        for (int j = 0; j < 4; j++)
            base[((slotb + j) ^ (kt & 7)) * 4 + reg] = vv[j];
    }

    for (int pass = 0; pass < 8; pass++) {
#pragma unroll
        for (int i = 0; i < 8; i++) {
            int q = tid + i * 256;
            int r = q >> 5, k4 = (q & 31) * 4;
            float4 v = *reinterpret_cast<const float4*>(&w2[(size_t)(pass * 64 + r) * K1C + k4]);
            float vv[4] = { tf32r(v.x), tf32r(v.y), tf32r(v.z), tf32r(v.w) };
            int nt = r >> 3, rr = r & 7;
            int kt = k4 >> 3, reg = (k4 & 7) >> 2;
            int slotb = rr * 4;
            float* base = Bs + (nt * 16 + kt) * 64;
#pragma unroll
            for (int j = 0; j < 4; j++)
                base[((slotb + j) ^ (kt & 7)) * 2 + reg] = vv[j];
        }
        __syncthreads();

        float d[2][4][4] = {};
#pragma unroll
        for (int kt = 0; kt < 16; kt++) {
            int lp = lane ^ (kt & 7);
            uint32_t a[2][4], b[4][2];
#pragma unroll
            for (int mi = 0; mi < 2; mi++) {
                int mt = wm * 2 + mi;
                *reinterpret_cast<float4*>(a[mi]) =
                    *reinterpret_cast<const float4*>(&As[(mt * 16 + kt) * 128 + lp * 4]);
            }
#pragma unroll
            for (int ni = 0; ni < 4; ni++) {
                int nt = wn * 4 + ni;
                *reinterpret_cast<float2*>(b[ni]) =
                    *reinterpret_cast<const float2*>(&Bs[(nt * 16 + kt) * 64 + lp * 2]);
            }
#pragma unroll
            for (int mi = 0; mi < 2; mi++)
#pragma unroll
                for (int ni = 0; ni < 4; ni++)
                    mma8(d[mi][ni], a[mi], b[ni]);
        }

#pragma unroll
        for (int ni = 0; ni < 4; ni++) {
#pragma unroll
            for (int par = 0; par < 2; par++) {
                int chp = wn * 32 + ni * 8 + tig * 2 + par;
                int ch = pass * 64 + chp;
                float bias = sb2[ch];
                float s = 0.f, qq = 0.f;
#pragma unroll
                for (int mi = 0; mi < 2; mi++) {
                    float v0 = d[mi][ni][par] + bias;
                    float v1 = d[mi][ni][par + 2] + bias;
                    s += v0 + v1;
                    qq = fmaf(v0, v0, qq); qq = fmaf(v1, v1, qq);
                }
#pragma unroll
                for (int o = 4; o < 32; o <<= 1) {
                    s  += __shfl_xor_sync(0xFFFFFFFFu, s, o);
                    qq += __shfl_xor_sync(0xFFFFFFFFu, qq, o);
                }
                if (gid == 0) { ps[wm * 64 + chp] = s; pq[wm * 64 + chp] = qq; }
            }
        }
        __syncthreads();
        if (tid < 64) {
            float s = ps[tid] + ps[64 + tid] + ps[128 + tid] + ps[192 + tid];
            float qq = pq[tid] + pq[64 + tid] + pq[128 + tid] + pq[192 + tid];
            g_p2s[(size_t)(pass * 64 + tid) * nblk + blockIdx.x] = s;
            g_p2q[(size_t)(pass * 64 + tid) * nblk + blockIdx.x] = qq;
        }
        __syncthreads();
    }
}

// ---------------- Pass 2: fused GEMM2-recompute + pooling ----------------
// smem floats:
constexpr int PG_BS   = 16384;            // Bs  (8192)
constexpr int PG_ATT  = 24576;            // attF (8192)
constexpr int PG_XS   = 32768;            // xs (128*40 = 5120)
constexpr int PG_PACC = 37888;            // pacc (512*33 = 16896)
constexpr int PG_SA1  = 54784;            // 128
constexpr int PG_SB1  = 54912;            // 128
constexpr int PG_SC2  = 55040;            // 512
constexpr int PG_SD2  = 55552;            // 512
constexpr int PG_SMEM_FLOATS = 56064;     // As at 0 (16384)

__global__ void __launch_bounds__(256, 1) k_poolg(const float* __restrict__ x,
                                                  const float* __restrict__ b2,
                                                  int L, int rpc) {
    extern __shared__ float sm[];
    float* As   = sm;
    float* Bs   = sm + PG_BS;
    float* attF = sm + PG_ATT;
    float* xs   = sm + PG_XS;
    float* pacc = sm + PG_PACC;
    float* sA1  = sm + PG_SA1;
    float* sB1  = sm + PG_SB1;
    float* sC2  = sm + PG_SC2;
    float* sD2  = sm + PG_SD2;
    const int tid = threadIdx.x, lane = tid & 31, warp = tid >> 5;
    const int wm = warp >> 1, wn = warp & 1;
    const int gid = lane >> 2, tig = lane & 3;
    const int b = blockIdx.x / SCH, s = blockIdx.x % SCH;
    const int pt0g = b * L + s * rpc;

    if (tid < 128) { sA1[tid] = g_a1[tid]; sB1[tid] = g_bb1[tid]; }
#pragma unroll
    for (int i = 0; i < 2; i++) {
        int ch = tid + i * 256;
        float a2 = g_a2[ch];
        sC2[ch] = a2;
        sD2[ch] = fmaf(__ldg(&b2[ch]), a2, g_bb2[ch]);
    }
    for (int i = tid; i < 512 * 33; i += 256) pacc[i] = 0.f;
    for (int i = tid; i < 128 * 8; i += 256) {
        int r = i >> 3, c = i & 7;
        xs[r * 40 + 32 + c] = (c == 0) ? 1.f : 0.f;
    }
    __syncthreads();

    const int ntile = rpc / 128;
    for (int pt = 0; pt < ntile; pt++) {
        const int row0 = pt0g + pt * 128;
        // stage As = tf32(relu(aff1(h)))  (fragment order, xor-swizzled)
#pragma unroll
        for (int i = 0; i < 16; i++) {
            int q = tid + i * 256;
            int r = q >> 5, k4 = (q & 31) * 4;
            float4 v = *reinterpret_cast<const float4*>(&g_h[(size_t)(row0 + r) * K1C + k4]);
            float vv[4];
            vv[0] = tf32r(fmaxf(fmaf(sA1[k4 + 0], v.x, sB1[k4 + 0]), 0.f));
            vv[1] = tf32r(fmaxf(fmaf(sA1[k4 + 1], v.y, sB1[k4 + 1]), 0.f));
            vv[2] = tf32r(fmaxf(fmaf(sA1[k4 + 2], v.z, sB1[k4 + 2]), 0.f));
            vv[3] = tf32r(fmaxf(fmaf(sA1[k4 + 3], v.w, sB1[k4 + 3]), 0.f));
            int mt = r >> 4, rr = r & 15;
            int kt = k4 >> 3, reg = (rr >> 3) + ((k4 & 7) >> 2) * 2;
            int slotb = (rr & 7) * 4;
            float* base = As + (mt * 16 + kt) * 128;
#pragma unroll
            for (int j = 0; j < 4; j++)
                base[((slotb + j) ^ (kt & 7)) * 4 + reg] = vv[j];
        }
        // stage xs (tf32 applied at frag load time is skipped: round now)
#pragma unroll
        for (int i = 0; i < 4; i++) {
            int q = tid + i * 256;
            int r = q >> 3, c4 = (q & 7) * 4;
            float4 v = *reinterpret_cast<const float4*>(&x[(size_t)(row0 + r) * C + c4]);
            xs[r * 40 + c4 + 0] = tf32r(v.x);
            xs[r * 40 + c4 + 1] = tf32r(v.y);
            xs[r * 40 + c4 + 2] = tf32r(v.z);
            xs[r * 40 + c4 + 3] = tf32r(v.w);
        }
        __syncthreads();

        for (int cp = 0; cp < 8; cp++) {
            // stage Bs = w2 slice [cp*64, +64)  (w2 from param via global symbol trick)
            // (w2 pointer passed via g_w2p)
            extern __device__ const float* g_w2p;
#pragma unroll
            for (int i = 0; i < 8; i++) {
                int q = tid + i * 256;
                int r = q >> 5, k4 = (q & 31) * 4;
                float4 v = *reinterpret_cast<const float4*>(&g_w2p[(size_t)(cp * 64 + r) * K1C + k4]);
                float vv[4] = { tf32r(v.x), tf32r(v.y), tf32r(v.z), tf32r(v.w) };
                int nt = r >> 3, rr = r & 7;
                int kt = k4 >> 3, reg = (k4 & 7) >> 2;
                int slotb = rr * 4;
                float* base = Bs + (nt * 16 + kt) * 64;
#pragma unroll
                for (int j = 0; j < 4; j++)
                    base[((slotb + j) ^ (kt & 7)) * 2 + reg] = vv[j];
            }
            __syncthreads();   // Bs ready; previous pool MMA done (attF free)

            float d[2][4][4] = {};
#pragma unroll
            for (int kt = 0; kt < 16; kt++) {
                int lp = lane ^ (kt & 7);
                uint32_t a[2][4], bb[4][2];
#pragma unroll
                for (int mi = 0; mi < 2; mi++) {
                    int mt = wm * 2 + mi;
                    *reinterpret_cast<float4*>(a[mi]) =
                        *reinterpret_cast<const float4*>(&As[(mt * 16 + kt) * 128 + lp * 4]);
                }
#pragma unroll
                for (int ni = 0; ni < 4; ni++) {
                    int nt = wn * 4 + ni;
                    *reinterpret_cast<float2*>(bb[ni]) =
                        *reinterpret_cast<const float2*>(&Bs[(nt * 16 + kt) * 64 + lp * 2]);
                }
#pragma unroll
                for (int mi = 0; mi < 2; mi++)
#pragma unroll
                    for (int ni = 0; ni < 4; ni++)
                        mma8(d[mi][ni], a[mi], bb[ni]);
            }

            // att = tf32(relu(d*a2 + (bb2 + b2*a2))) -> attF (transposed frag order)
#pragma unroll
            for (int mi = 0; mi < 2; mi++)
#pragma unroll
                for (int ni = 0; ni < 4; ni++)
#pragma unroll
                    for (int e = 0; e < 4; e++) {
                        int rL = wm * 32 + mi * 16 + gid + ((e >> 1) << 3);
                        int cL = wn * 32 + ni * 8 + tig * 2 + (e & 1);
                        int ch = cp * 64 + cL;
                        float v = tf32r(fmaxf(fmaf(d[mi][ni][e], sC2[ch], sD2[ch]), 0.f));
                        attF[((cL >> 4) * 16 + (rL >> 3)) * 128 + (cL & 15) * 8 + (rL & 7)] = v;
                    }
            __syncthreads();   // attF ready

            // pool MMA: D2[64ch x 40] += attF[64ch x 128pt] @ xs[128pt x 40]
            const int mt2 = warp >> 1, half = warp & 1;
            const int nbase = half * 3, ncount = half ? 2 : 3;
            float d2[3][4] = {};
#pragma unroll
            for (int kt2 = 0; kt2 < 16; kt2++) {
                const float* ab = &attF[(mt2 * 16 + kt2) * 128];
                uint32_t a2f[4];
                a2f[0] = __float_as_uint(ab[gid * 8 + tig]);
                a2f[1] = __float_as_uint(ab[(gid + 8) * 8 + tig]);
                a2f[2] = __float_as_uint(ab[gid * 8 + tig + 4]);
                a2f[3] = __float_as_uint(ab[(gid + 8) * 8 + tig + 4]);
#pragma unroll
                for (int ni2 = 0; ni2 < 3; ni2++) {
                    if (ni2 < ncount) {
                        const float* br = &xs[(kt2 * 8 + tig) * 40 + (nbase + ni2) * 8 + gid];
                        uint32_t bb2f[2];
                        bb2f[0] = __float_as_uint(br[0]);
                        bb2f[1] = __float_as_uint(br[4 * 40]);
                        mma8(d2[ni2], a2f, bb2f);
                    }
                }
            }
#pragma unroll
            for (int ni2 = 0; ni2 < 3; ni2++) {
                if (ni2 < ncount) {
#pragma unroll
                    for (int e = 0; e < 4; e++) {
                        int ch = cp * 64 + mt2 * 16 + gid + ((e >> 1) << 3);
                        int n = (nbase + ni2) * 8 + tig * 2 + (e & 1);
                        if (n <= 32) pacc[ch * 33 + n] += d2[ni2][e];
                    }
                }
            }
            __syncthreads();   // pacc RMW done; Bs/attF free for next cp
        }
    }

    // write partials
    const int seg = blockIdx.x;
    for (int i = tid; i < 512 * 33; i += 256) {
        int ch = i / 33, n = i % 33;
        float v = pacc[i];
        if (n < 32) g_ppool[((size_t)seg * K2C + ch) * C + n] = v;
        else        g_pgp[(size_t)seg * K2C + ch] = v;
    }
}
__device__ const float* g_w2p;

__global__ void k_setw2(const float* w2) { g_w2p = w2; }

__global__ void k_poolred(float invL, int B) {
    int idx = blockIdx.x * 256 + threadIdx.x;
    if (idx >= B * K2C * C) return;
    int b = idx / (K2C * C), rem = idx % (K2C * C);
    float s = 0.f;
#pragma unroll
    for (int t = 0; t < SCH; t++) s += g_ppool[(size_t)(b * SCH + t) * (K2C * C) + rem];
    g_pooled[idx] = s * invL;
}
__global__ void k_gpred(float* __restrict__ out, int B, int L) {
    int idx = blockIdx.x * 256 + threadIdx.x;
    if (idx >= B * K2C) return;
    int b = idx / K2C, k = idx % K2C;
    float s = 0.f;
#pragma unroll
    for (int t = 0; t < SCH; t++) s += g_pgp[(size_t)(b * SCH + t) * K2C + k];
    out[(size_t)B * FCC + (size_t)b * K2C + k] = s;
    if (k == 0) out[(size_t)B * (FCC + K2C) + b] = (float)L;
}

// ---------------- final FC + BN + L2 norm ----------------
__global__ void __launch_bounds__(128) k_final(const float* __restrict__ wf,
                                               const float* __restrict__ bf,
                                               const float* __restrict__ gf,
                                               const float* __restrict__ bef, int B) {
    const int f = blockIdx.x, tid = threadIdx.x, nq = (K2C * C) / 4;
    float acc[MAXB];
#pragma unroll
    for (int b = 0; b < MAXB; b++) acc[b] = 0.f;
    const float4* wf4 = reinterpret_cast<const float4*>(wf) + (size_t)f * nq;
    const float4* p4 = reinterpret_cast<const float4*>(g_pooled);
    for (int i = tid; i < nq; i += 128) {
        float4 wv = wf4[i];
        for (int b = 0; b < B; b++) {
            float4 pv = p4[(size_t)b * nq + i];
            acc[b] += wv.x * pv.x + wv.y * pv.y + wv.z * pv.z + wv.w * pv.w;
        }
    }
    __shared__ float red[MAXB * 128];
    for (int b = 0; b < B; b++) red[b * 128 + tid] = acc[b];
    __syncthreads();
    for (int o = 64; o > 0; o >>= 1) {
        if (tid < o)
            for (int b = 0; b < B; b++) red[b * 128 + tid] += red[b * 128 + tid + o];
        __syncthreads();
    }
    __shared__ float sv[MAXB], smu, srstd;
    if (tid < B) sv[tid] = red[tid * 128] + bf[f];
    __syncthreads();
    if (tid == 0) {
        float mu = 0.f;
        for (int b = 0; b < B; b++) mu += sv[b];
        mu /= (float)B;
        float var = 0.f;
        for (int b = 0; b < B; b++) { float dd = sv[b] - mu; var += dd * dd; }
        var /= (float)B;
        smu = mu; srstd = rsqrtf(var + EPS_BN);
    }
    __syncthreads();
    if (tid < B) g_resb[tid * FCC + f] = (sv[tid] - smu) * srstd * gf[f] + bef[f];
}

__global__ void __launch_bounds__(FCC) k_norm(float* __restrict__ out) {
    const int b = blockIdx.x, f = threadIdx.x;
    float v = g_resb[b * FCC + f];
    __shared__ float red[FCC];
    red[f] = v * v; __syncthreads();
    for (int o = FCC / 2; o > 0; o >>= 1) {
        if (f < o) red[f] += red[f + o];
        __syncthreads();
    }
    __shared__ float sinv;
    if (f == 0) sinv = 1.f / fmaxf(sqrtf(red[0]), 1e-12f);
    __syncthreads();
    out[(size_t)b * FCC + f] = v * sinv;
}

// ---------------------------------------------------------------------------
extern "C" void kernel_launch(void* const* d_in, const int* in_sizes, int n_in,
                              void* d_out, int out_size) {
    const float* x   = (const float*)d_in[0];
    const float* w1  = (const float*)d_in[1];
    const float* b1  = (const float*)d_in[2];
    const float* g1  = (const float*)d_in[3];
    const float* be1 = (const float*)d_in[4];
    const float* w2  = (const float*)d_in[5];
    const float* b2  = (const float*)d_in[6];
    const float* g2  = (const float*)d_in[7];
    const float* be2 = (const float*)d_in[8];
    const float* wf  = (const float*)d_in[9];
    const float* bf  = (const float*)d_in[10];
    const float* gf  = (const float*)d_in[11];
    const float* bef = (const float*)d_in[12];
    float* out = (float*)d_out;

    const int N = in_sizes[0] / C;
    const int B = out_size / (FCC + K2C + 1);
    const int L = N / B;
    const int rpc = L / SCH;
    const int nblk2 = N / 128;
    const int s2smem = S2_SMEM_FLOATS * 4;
    const int pgsmem = PG_SMEM_FLOATS * 4;

    cudaFuncSetAttribute(k_stat2, cudaFuncAttributeMaxDynamicSharedMemorySize, s2smem);
    cudaFuncSetAttribute(k_poolg, cudaFuncAttributeMaxDynamicSharedMemorySize, pgsmem);

    k_setw2<<<1, 1>>>(w2);
    k_gemm1<<<N / 256, 128>>>(x, w1, b1);
    k_fin1<<<K1C, 256>>>(g1, be1, N / 256, 1.f / (float)N);
    k_stat2<<<nblk2, 256, s2smem>>>(w2, b2, nblk2);
    k_fin2<<<K2C, 256>>>(g2, be2, nblk2, 1.f / (float)N);
    k_poolg<<<B * SCH, 256, pgsmem>>>(x, b2, L, rpc);
    k_poolred<<<(B * K2C * C + 255) / 256, 256>>>(1.f / (float)L, B);
    k_gpred<<<(B * K2C + 255) / 256, 256>>>(out, B, L);
    k_final<<<FCC, 128>>>(wf, bf, gf, bef, B);
    k_norm<<<B, FCC>>>(out);
}

// round 8
// speedup vs baseline: 1.8281x; 1.8281x over previous
#include <cuda_runtime.h>
#include <cuda_fp16.h>
#include <cstdint>

constexpr int C = 32, K1C = 128, K2C = 512, FCC = 256;
constexpr int MAXN = 524288, MAXB = 16, SCH = 16;
constexpr float EPS_BN = 1e-5f;

__device__ float  g_h  [(size_t)MAXN * K1C];          // h_pre fp32 [N][128]
__device__ __half g_att[(size_t)K2C * MAXN];          // attT fp16 [512][N]
__device__ float g_p1s [(MAXN / 256) * K1C];
__device__ float g_p1q [(MAXN / 256) * K1C];
__device__ float g_p2s [(size_t)K2C * (MAXN / 128)];  // [ch][blk]
__device__ float g_p2q [(size_t)K2C * (MAXN / 128)];
__device__ float g_a1[K1C], g_bb1[K1C], g_a2[K2C], g_bb2[K2C];
__device__ float g_ppool[(size_t)MAXB * SCH * K2C * C];
__device__ float g_pgp  [(size_t)MAXB * SCH * K2C];
__device__ float g_pooled[(size_t)MAXB * K2C * C];
__device__ float g_resb [MAXB * FCC];

__device__ __forceinline__ float tf32r(float v) {
    float o; asm("cvt.rna.tf32.f32 %0, %1;" : "=f"(o) : "f"(v)); return o;
}
__device__ __forceinline__ void mma8(float* d, const uint32_t* a, const uint32_t* b) {
    asm volatile(
        "mma.sync.aligned.m16n8k8.row.col.f32.tf32.tf32.f32 "
        "{%0,%1,%2,%3}, {%4,%5,%6,%7}, {%8,%9}, {%0,%1,%2,%3};"
        : "+f"(d[0]), "+f"(d[1]), "+f"(d[2]), "+f"(d[3])
        : "r"(a[0]), "r"(a[1]), "r"(a[2]), "r"(a[3]), "r"(b[0]), "r"(b[1]));
}
__device__ __forceinline__ uint32_t s2u(const void* p) {
    uint32_t a;
    asm("{ .reg .u64 t; cvta.to.shared.u64 t, %1; cvt.u32.u64 %0, t; }" : "=r"(a) : "l"(p));
    return a;
}
__device__ __forceinline__ void cpasync16(uint32_t saddr, const void* g) {
    asm volatile("cp.async.cg.shared.global [%0], [%1], 16;" :: "r"(saddr), "l"(g));
}
#define CP_COMMIT() asm volatile("cp.async.commit_group;" ::: "memory")
#define CP_WAIT(n)  asm volatile("cp.async.wait_group %0;" :: "n"(n) : "memory")

// ---------------- GEMM1 (fp32 SIMT) ----------------
__global__ void __launch_bounds__(128) k_gemm1(const float* __restrict__ x,
                                               const float* __restrict__ w1,
                                               const float* __restrict__ b1) {
    __shared__ float sx[256 * C];
    const int k = threadIdx.x, p0 = blockIdx.x * 256;
    const float4* xg = reinterpret_cast<const float4*>(x) + (size_t)p0 * (C / 4);
    float4* sx4 = reinterpret_cast<float4*>(sx);
#pragma unroll
    for (int i = 0; i < 16; i++) sx4[threadIdx.x + i * 128] = xg[threadIdx.x + i * 128];
    float w[C];
#pragma unroll
    for (int c = 0; c < C; c++) w[c] = __ldg(&w1[k * C + c]);
    const float bias = __ldg(&b1[k]);
    __syncthreads();
    float s = 0.f, q = 0.f;
    float* hp = g_h + (size_t)p0 * K1C + k;
    for (int p = 0; p < 256; p++) {
        const float4* xr = reinterpret_cast<const float4*>(sx + p * C);
        float acc = bias;
#pragma unroll
        for (int c4 = 0; c4 < 8; c4++) {
            float4 v = xr[c4];
            acc = fmaf(w[c4 * 4 + 0], v.x, acc);
            acc = fmaf(w[c4 * 4 + 1], v.y, acc);
            acc = fmaf(w[c4 * 4 + 2], v.z, acc);
            acc = fmaf(w[c4 * 4 + 3], v.w, acc);
        }
        hp[(size_t)p * K1C] = acc;
        s += acc; q = fmaf(acc, acc, q);
    }
    g_p1s[blockIdx.x * K1C + k] = s;
    g_p1q[blockIdx.x * K1C + k] = q;
}

// ---------------- BN finalize ----------------
__global__ void k_fin1(const float* __restrict__ g, const float* __restrict__ be,
                       int nblk, float invN) {
    const int ch = blockIdx.x;
    __shared__ float rs[256], rq[256];
    float s = 0.f, q = 0.f;
    for (int i = threadIdx.x; i < nblk; i += 256) {
        s += g_p1s[i * K1C + ch]; q += g_p1q[i * K1C + ch];
    }
    rs[threadIdx.x] = s; rq[threadIdx.x] = q; __syncthreads();
    for (int o = 128; o > 0; o >>= 1) {
        if (threadIdx.x < o) { rs[threadIdx.x] += rs[threadIdx.x + o]; rq[threadIdx.x] += rq[threadIdx.x + o]; }
        __syncthreads();
    }
    if (threadIdx.x == 0) {
        float mu = rs[0] * invN, var = rq[0] * invN - mu * mu;
        float a = g[ch] * rsqrtf(var + EPS_BN);
        g_a1[ch] = a; g_bb1[ch] = be[ch] - mu * a;
    }
}
__global__ void k_fin2(const float* __restrict__ g, const float* __restrict__ be,
                       int nblk, float invN) {
    const int ch = blockIdx.x;
    __shared__ float rs[256], rq[256];
    float s = 0.f, q = 0.f;
    const float* ps = g_p2s + (size_t)ch * nblk;
    const float* pq = g_p2q + (size_t)ch * nblk;
    for (int i = threadIdx.x; i < nblk; i += 256) { s += ps[i]; q += pq[i]; }
    rs[threadIdx.x] = s; rq[threadIdx.x] = q; __syncthreads();
    for (int o = 128; o > 0; o >>= 1) {
        if (threadIdx.x < o) { rs[threadIdx.x] += rs[threadIdx.x + o]; rq[threadIdx.x] += rq[threadIdx.x + o]; }
        __syncthreads();
    }
    if (threadIdx.x == 0) {
        float mu = rs[0] * invN, var = rq[0] * invN - mu * mu;
        float a = g[ch] * rsqrtf(var + EPS_BN);
        g_a2[ch] = a; g_bb2[ch] = be[ch] - mu * a;
    }
}

// ---------------- GEMM2: tf32 mma.sync, 8 N-passes of 64, 2 CTAs/SM --------
constexpr int G2_OFF_BS = 16384, G2_OFF_SA1 = 24576, G2_OFF_SB1 = 24704;
constexpr int G2_OFF_SB2 = 24832, G2_OFF_PS = 25344, G2_OFF_PQ = 25600;
constexpr int G2_SMEM_FLOATS = 25856;

__global__ void __launch_bounds__(256, 2) k_gemm2(const float* __restrict__ w2,
                                                  const float* __restrict__ b2,
                                                  int Np, int nblk) {
    extern __shared__ float sm[];
    float* As = sm;
    float* Bs = sm + G2_OFF_BS;
    float* sA1 = sm + G2_OFF_SA1;
    float* sB1 = sm + G2_OFF_SB1;
    float* sb2 = sm + G2_OFF_SB2;
    float* ps  = sm + G2_OFF_PS;
    float* pq  = sm + G2_OFF_PQ;
    const int tid = threadIdx.x, lane = tid & 31, warp = tid >> 5;
    const int wm = warp >> 1, wn = warp & 1;
    const int gid = lane >> 2, tig = lane & 3;
    const int row0 = blockIdx.x * 128;

    if (tid < 128) { sA1[tid] = g_a1[tid]; sB1[tid] = g_bb1[tid]; }
    sb2[tid] = __ldg(&b2[tid]); sb2[tid + 256] = __ldg(&b2[tid + 256]);
    __syncthreads();

    // stage A = tf32(relu(aff1(h)))  (fragment order, xor-swizzled)
#pragma unroll
    for (int i = 0; i < 16; i++) {
        int q = tid + i * 256;
        int r = q >> 5, k4 = (q & 31) * 4;
        float4 v = *reinterpret_cast<const float4*>(&g_h[(size_t)(row0 + r) * K1C + k4]);
        float vv[4];
        vv[0] = tf32r(fmaxf(fmaf(sA1[k4 + 0], v.x, sB1[k4 + 0]), 0.f));
        vv[1] = tf32r(fmaxf(fmaf(sA1[k4 + 1], v.y, sB1[k4 + 1]), 0.f));
        vv[2] = tf32r(fmaxf(fmaf(sA1[k4 + 2], v.z, sB1[k4 + 2]), 0.f));
        vv[3] = tf32r(fmaxf(fmaf(sA1[k4 + 3], v.w, sB1[k4 + 3]), 0.f));
        int mt = r >> 4, rr = r & 15;
        int kt = k4 >> 3, reg = (rr >> 3) + ((k4 & 7) >> 2) * 2;
        int slotb = (rr & 7) * 4;
        float* base = As + (mt * 16 + kt) * 128;
#pragma unroll
        for (int j = 0; j < 4; j++)
            base[((slotb + j) ^ (kt & 7)) * 4 + reg] = vv[j];
    }

    for (int pass = 0; pass < 8; pass++) {
#pragma unroll
        for (int i = 0; i < 8; i++) {
            int q = tid + i * 256;
            int r = q >> 5, k4 = (q & 31) * 4;
            float4 v = *reinterpret_cast<const float4*>(&w2[(size_t)(pass * 64 + r) * K1C + k4]);
            float vv[4] = { tf32r(v.x), tf32r(v.y), tf32r(v.z), tf32r(v.w) };
            int nt = r >> 3, rr = r & 7;
            int kt = k4 >> 3, reg = (k4 & 7) >> 2;
            int slotb = rr * 4;
            float* base = Bs + (nt * 16 + kt) * 64;
#pragma unroll
            for (int j = 0; j < 4; j++)
                base[((slotb + j) ^ (kt & 7)) * 2 + reg] = vv[j];
        }
        __syncthreads();

        float d[2][4][4] = {};
#pragma unroll
        for (int kt = 0; kt < 16; kt++) {
            int lp = lane ^ (kt & 7);
            uint32_t a[2][4], b[4][2];
#pragma unroll
            for (int mi = 0; mi < 2; mi++) {
                int mt = wm * 2 + mi;
                *reinterpret_cast<float4*>(a[mi]) =
                    *reinterpret_cast<const float4*>(&As[(mt * 16 + kt) * 128 + lp * 4]);
            }
#pragma unroll
            for (int ni = 0; ni < 4; ni++) {
                int nt = wn * 4 + ni;
                *reinterpret_cast<float2*>(b[ni]) =
                    *reinterpret_cast<const float2*>(&Bs[(nt * 16 + kt) * 64 + lp * 2]);
            }
#pragma unroll
            for (int mi = 0; mi < 2; mi++)
#pragma unroll
                for (int ni = 0; ni < 4; ni++)
                    mma8(d[mi][ni], a[mi], b[ni]);
        }

        // epilogue: bias, store attT fp16, BN2 partials from fp32 accumulators
#pragma unroll
        for (int ni = 0; ni < 4; ni++) {
#pragma unroll
            for (int par = 0; par < 2; par++) {
                int chp = wn * 32 + ni * 8 + tig * 2 + par;
                int ch = pass * 64 + chp;
                float bias = sb2[ch];
                float s = 0.f, qq = 0.f;
#pragma unroll
                for (int mi = 0; mi < 2; mi++) {
                    float v0 = d[mi][ni][par] + bias;
                    float v1 = d[mi][ni][par + 2] + bias;
                    int ptb = row0 + wm * 32 + mi * 16 + gid;
                    g_att[(size_t)ch * Np + ptb]     = __float2half_rn(v0);
                    g_att[(size_t)ch * Np + ptb + 8] = __float2half_rn(v1);
                    s += v0 + v1;
                    qq = fmaf(v0, v0, qq); qq = fmaf(v1, v1, qq);
                }
#pragma unroll
                for (int o = 4; o < 32; o <<= 1) {
                    s  += __shfl_xor_sync(0xFFFFFFFFu, s, o);
                    qq += __shfl_xor_sync(0xFFFFFFFFu, qq, o);
                }
                if (gid == 0) { ps[wm * 64 + chp] = s; pq[wm * 64 + chp] = qq; }
            }
        }
        __syncthreads();
        if (tid < 64) {
            float s = ps[tid] + ps[64 + tid] + ps[128 + tid] + ps[192 + tid];
            float qq = pq[tid] + pq[64 + tid] + pq[128 + tid] + pq[192 + tid];
            g_p2s[(size_t)(pass * 64 + tid) * nblk + blockIdx.x] = s;
            g_p2q[(size_t)(pass * 64 + tid) * nblk + blockIdx.x] = qq;
        }
        __syncthreads();
    }
}

// ---------------- Pool: cp.async double-buffered, fp16 att, tf32 mma -------
// bytes: attb half[2][128][72] = 36864 | xb f32[2][64][40] = 20480 | sA2/sB2 1024
constexpr int P_AS2 = 72;                       // half elems per att row
constexpr int P_XS = 40;
constexpr int P_OFF_XB = 36864;
constexpr int P_OFF_SA2 = P_OFF_XB + 20480;     // 57344
constexpr int P_SMEM_BYTES = P_OFF_SA2 + 1024;  // 58368

__global__ void __launch_bounds__(256) k_pool(const float* __restrict__ x,
                                              int Np, int L, int rpc) {
    extern __shared__ char psmc[];
    __half* attb = reinterpret_cast<__half*>(psmc);
    float* xb   = reinterpret_cast<float*>(psmc + P_OFF_XB);
    float* sA2  = reinterpret_cast<float*>(psmc + P_OFF_SA2);
    float* sB2c = sA2 + 128;
    const int tid = threadIdx.x, lane = tid & 31, warp = tid >> 5;
    const int gid = lane >> 2, tig = lane & 3;
    const int ch0 = blockIdx.x * 128;
    const int b = blockIdx.y / SCH, s = blockIdx.y % SCH;
    const int pt0g = b * L + s * rpc;
    const int nc = rpc / 64;
    const uint32_t attb_u = s2u(attb), xb_u = s2u(xb);

    if (tid < 128) { sA2[tid] = g_a2[ch0 + tid]; sB2c[tid] = g_bb2[ch0 + tid]; }
    for (int i = tid; i < 2 * 64 * 8; i += 256) {
        int buf = i / 512, r = (i / 8) % 64, c = i & 7;
        xb[buf * 64 * P_XS + r * P_XS + 32 + c] = (c == 0) ? 1.f : 0.f;
    }

    auto issue = [&](int ck, int buf) {
        const __half* ga = &g_att[(size_t)ch0 * Np + pt0g + ck * 64];
        uint32_t sa = attb_u + buf * (128 * P_AS2 * 2);
#pragma unroll
        for (int i = 0; i < 4; i++) {
            int q = tid + i * 256;
            int r = q >> 3, c = q & 7;
            cpasync16(sa + (uint32_t)(r * P_AS2 * 2 + c * 16), ga + (size_t)r * Np + c * 8);
        }
        const float* gx = &x[(size_t)(pt0g + ck * 64) * C];
        uint32_t sx = xb_u + buf * (64 * P_XS * 4);
#pragma unroll
        for (int i = 0; i < 2; i++) {
            int q = tid + i * 256;
            int r = q >> 3, c = q & 7;
            cpasync16(sx + (uint32_t)(r * P_XS + c * 4) * 4, gx + r * C + c * 4);
        }
    };

    const float cA0 = g_a2[ch0 + warp * 16 + gid],     cB0 = g_bb2[ch0 + warp * 16 + gid];
    const float cA1 = g_a2[ch0 + warp * 16 + gid + 8], cB1 = g_bb2[ch0 + warp * 16 + gid + 8];

    float d[5][4] = {};
    issue(0, 0);
    CP_COMMIT();

    for (int ck = 0; ck < nc; ck++) {
        if (ck + 1 < nc) { issue(ck + 1, (ck + 1) & 1); CP_COMMIT(); CP_WAIT(1); }
        else             { CP_WAIT(0); }
        __syncthreads();

        const __half* ab = attb + (ck & 1) * (128 * P_AS2);
        const float* xv = xb + (ck & 1) * (64 * P_XS);
        const __half* ar0 = ab + (warp * 16 + gid) * P_AS2;
        const __half* ar1 = ar0 + 8 * P_AS2;
#pragma unroll
        for (int kt = 0; kt < 8; kt++) {
            uint32_t a[4];
            a[0] = __float_as_uint(tf32r(fmaxf(fmaf(cA0, __half2float(ar0[kt * 8 + tig]), cB0), 0.f)));
            a[1] = __float_as_uint(tf32r(fmaxf(fmaf(cA1, __half2float(ar1[kt * 8 + tig]), cB1), 0.f)));
            a[2] = __float_as_uint(tf32r(fmaxf(fmaf(cA0, __half2float(ar0[kt * 8 + tig + 4]), cB0), 0.f)));
            a[3] = __float_as_uint(tf32r(fmaxf(fmaf(cA1, __half2float(ar1[kt * 8 + tig + 4]), cB1), 0.f)));
#pragma unroll
            for (int ni = 0; ni < 5; ni++) {
                const float* br = xv + (kt * 8 + tig) * P_XS + ni * 8 + gid;
                uint32_t bb[2];
                bb[0] = __float_as_uint(tf32r(br[0]));
                bb[1] = __float_as_uint(tf32r(br[4 * P_XS]));
                mma8(d[ni], a, bb);
            }
        }
        __syncthreads();
    }

    const int seg = b * SCH + s;
#pragma unroll
    for (int ni = 0; ni < 5; ni++) {
#pragma unroll
        for (int c = 0; c < 4; c++) {
            int n = ni * 8 + tig * 2 + (c & 1);
            int ch = ch0 + warp * 16 + gid + 8 * (c >> 1);
            if (n < 32)
                g_ppool[((size_t)seg * K2C + ch) * C + n] = d[ni][c];
            else if (n == 32)
                g_pgp[(size_t)seg * K2C + ch] = d[ni][c];
        }
    }
}

__global__ void k_poolred(float invL, int B) {
    int idx = blockIdx.x * 256 + threadIdx.x;
    if (idx >= B * K2C * C) return;
    int b = idx / (K2C * C), rem = idx % (K2C * C);
    float s = 0.f;
#pragma unroll
    for (int t = 0; t < SCH; t++) s += g_ppool[(size_t)(b * SCH + t) * (K2C * C) + rem];
    g_pooled[idx] = s * invL;
}
__global__ void k_gpred(float* __restrict__ out, int B, int L) {
    int idx = blockIdx.x * 256 + threadIdx.x;
    if (idx >= B * K2C) return;
    int b = idx / K2C, k = idx % K2C;
    float s = 0.f;
#pragma unroll
    for (int t = 0; t < SCH; t++) s += g_pgp[(size_t)(b * SCH + t) * K2C + k];
    out[(size_t)B * FCC + (size_t)b * K2C + k] = s;
    if (k == 0) out[(size_t)B * (FCC + K2C) + b] = (float)L;
}

// ---------------- final FC + BN + L2 norm ----------------
__global__ void __launch_bounds__(128) k_final(const float* __restrict__ wf,
                                               const float* __restrict__ bf,
                                               const float* __restrict__ gf,
                                               const float* __restrict__ bef, int B) {
    const int f = blockIdx.x, tid = threadIdx.x, nq = (K2C * C) / 4;
    float acc[MAXB];
#pragma unroll
    for (int b = 0; b < MAXB; b++) acc[b] = 0.f;
    const float4* wf4 = reinterpret_cast<const float4*>(wf) + (size_t)f * nq;
    const float4* p4 = reinterpret_cast<const float4*>(g_pooled);
    for (int i = tid; i < nq; i += 128) {
        float4 wv = wf4[i];
        for (int b = 0; b < B; b++) {
            float4 pv = p4[(size_t)b * nq + i];
            acc[b] += wv.x * pv.x + wv.y * pv.y + wv.z * pv.z + wv.w * pv.w;
        }
    }
    __shared__ float red[MAXB * 128];
    for (int b = 0; b < B; b++) red[b * 128 + tid] = acc[b];
    __syncthreads();
    for (int o = 64; o > 0; o >>= 1) {
        if (tid < o)
            for (int b = 0; b < B; b++) red[b * 128 + tid] += red[b * 128 + tid + o];
        __syncthreads();
    }
    __shared__ float sv[MAXB], smu, srstd;
    if (tid < B) sv[tid] = red[tid * 128] + bf[f];
    __syncthreads();
    if (tid == 0) {
        float mu = 0.f;
        for (int b = 0; b < B; b++) mu += sv[b];
        mu /= (float)B;
        float var = 0.f;
        for (int b = 0; b < B; b++) { float dd = sv[b] - mu; var += dd * dd; }
        var /= (float)B;
        smu = mu; srstd = rsqrtf(var + EPS_BN);
    }
    __syncthreads();
    if (tid < B) g_resb[tid * FCC + f] = (sv[tid] - smu) * srstd * gf[f] + bef[f];
}

__global__ void __launch_bounds__(FCC) k_norm(float* __restrict__ out) {
    const int b = blockIdx.x, f = threadIdx.x;
    float v = g_resb[b * FCC + f];
    __shared__ float red[FCC];
    red[f] = v * v; __syncthreads();
    for (int o = FCC / 2; o > 0; o >>= 1) {
        if (f < o) red[f] += red[f + o];
        __syncthreads();
    }
    __shared__ float sinv;
    if (f == 0) sinv = 1.f / fmaxf(sqrtf(red[0]), 1e-12f);
    __syncthreads();
    out[(size_t)b * FCC + f] = v * sinv;
}

// ---------------------------------------------------------------------------
extern "C" void kernel_launch(void* const* d_in, const int* in_sizes, int n_in,
                              void* d_out, int out_size) {
    const float* x   = (const float*)d_in[0];
    const float* w1  = (const float*)d_in[1];
    const float* b1  = (const float*)d_in[2];
    const float* g1  = (const float*)d_in[3];
    const float* be1 = (const float*)d_in[4];
    const float* w2  = (const float*)d_in[5];
    const float* b2  = (const float*)d_in[6];
    const float* g2  = (const float*)d_in[7];
    const float* be2 = (const float*)d_in[8];
    const float* wf  = (const float*)d_in[9];
    const float* bf  = (const float*)d_in[10];
    const float* gf  = (const float*)d_in[11];
    const float* bef = (const float*)d_in[12];
    float* out = (float*)d_out;

    const int N = in_sizes[0] / C;
    const int B = out_size / (FCC + K2C + 1);
    const int L = N / B;
    const int rpc = L / SCH;
    const int nblk2 = N / 128;
    const int g2smem = G2_SMEM_FLOATS * 4;

    cudaFuncSetAttribute(k_gemm2, cudaFuncAttributeMaxDynamicSharedMemorySize, g2smem);
    cudaFuncSetAttribute(k_pool, cudaFuncAttributeMaxDynamicSharedMemorySize, P_SMEM_BYTES);

    k_gemm1<<<N / 256, 128>>>(x, w1, b1);
    k_fin1<<<K1C, 256>>>(g1, be1, N / 256, 1.f / (float)N);
    k_gemm2<<<nblk2, 256, g2smem>>>(w2, b2, N, nblk2);
    k_fin2<<<K2C, 256>>>(g2, be2, nblk2, 1.f / (float)N);
    k_pool<<<dim3(K2C / 128, B * SCH), 256, P_SMEM_BYTES>>>(x, N, L, rpc);
    k_poolred<<<(B * K2C * C + 255) / 256, 256>>>(1.f / (float)L, B);
    k_gpred<<<(B * K2C + 255) / 256, 256>>>(out, B, L);
    k_final<<<FCC, 128>>>(wf, bf, gf, bef, B);
    k_norm<<<B, FCC>>>(out);
}

// round 13
// speedup vs baseline: 1.9663x; 1.0756x over previous
#include <cuda_runtime.h>
#include <cuda_fp16.h>
#include <cstdint>

constexpr int C = 32, K1C = 128, K2C = 512, FCC = 256;
constexpr int MAXN = 524288, MAXB = 16, SCH = 16;
constexpr float EPS_BN = 1e-5f;

__device__ __half g_att[(size_t)K2C * MAXN];          // attT fp16 [512][N]
__device__ float g_p1s [(MAXN / 256) * K1C];
__device__ float g_p1q [(MAXN / 256) * K1C];
__device__ float g_p2s [(size_t)K2C * (MAXN / 128)];  // [ch][blk]
__device__ float g_p2q [(size_t)K2C * (MAXN / 128)];
__device__ float g_a1[K1C], g_bb1[K1C], g_a2[K2C], g_bb2[K2C];
__device__ float g_ppool[(size_t)MAXB * SCH * K2C * C];
__device__ float g_pgp  [(size_t)MAXB * SCH * K2C];
__device__ float g_pooled[(size_t)MAXB * K2C * C];
__device__ float g_resb [MAXB * FCC];

__device__ __forceinline__ float tf32r(float v) {
    float o; asm("cvt.rna.tf32.f32 %0, %1;" : "=f"(o) : "f"(v)); return o;
}
__device__ __forceinline__ void mma8(float* d, const uint32_t* a, const uint32_t* b) {
    asm volatile(
        "mma.sync.aligned.m16n8k8.row.col.f32.tf32.tf32.f32 "
        "{%0,%1,%2,%3}, {%4,%5,%6,%7}, {%8,%9}, {%0,%1,%2,%3};"
        : "+f"(d[0]), "+f"(d[1]), "+f"(d[2]), "+f"(d[3])
        : "r"(a[0]), "r"(a[1]), "r"(a[2]), "r"(a[3]), "r"(b[0]), "r"(b[1]));
}
__device__ __forceinline__ uint32_t s2u(const void* p) {
    uint32_t a;
    asm("{ .reg .u64 t; cvta.to.shared.u64 t, %1; cvt.u32.u64 %0, t; }" : "=r"(a) : "l"(p));
    return a;
}
__device__ __forceinline__ void cpasync16(uint32_t saddr, const void* g) {
    asm volatile("cp.async.cg.shared.global [%0], [%1], 16;" :: "r"(saddr), "l"(g));
}
#define CP_COMMIT() asm volatile("cp.async.commit_group;" ::: "memory")
#define CP_WAIT(n)  asm volatile("cp.async.wait_group %0;" :: "n"(n) : "memory")

// =============== k_stat1: BN1 stats via tf32 MMA (no h materialization) =====
// tile: 256 pts x 128 ch, K=32.  smem floats: Ax 8192 | Bw1 4096 | sb1 128 |
// ps 512 | pq 512  = 13440
constexpr int S1_BW1 = 8192, S1_SB1 = 12288, S1_PS = 12416, S1_PQ = 12928;
constexpr int S1_SMEM_FLOATS = 13440;

__global__ void __launch_bounds__(256, 2) k_stat1(const float* __restrict__ x,
                                                  const float* __restrict__ w1,
                                                  const float* __restrict__ b1) {
    extern __shared__ float sm[];
    float* Ax  = sm;
    float* Bw1 = sm + S1_BW1;
    float* sb1 = sm + S1_SB1;
    float* ps  = sm + S1_PS;
    float* pq  = sm + S1_PQ;
    const int tid = threadIdx.x, lane = tid & 31, warp = tid >> 5;
    const int gid = lane >> 2, tig = lane & 3;
    const int p0 = blockIdx.x * 256;

    if (tid < 128) sb1[tid] = __ldg(&b1[tid]);
    // stage x[256][32] in A-frag order, xor-swizzled by kt (kt<4)
#pragma unroll
    for (int i = 0; i < 8; i++) {
        int q = tid + i * 256;
        int r = q >> 3, k4 = (q & 7) * 4;
        float4 v = *reinterpret_cast<const float4*>(&x[(size_t)(p0 + r) * C + k4]);
        float vv[4] = { tf32r(v.x), tf32r(v.y), tf32r(v.z), tf32r(v.w) };
        int mt = r >> 4, rr = r & 15;
        int kt = k4 >> 3, reg = (rr >> 3) + ((k4 & 7) >> 2) * 2;
        int slotb = (rr & 7) * 4;
        float* base = Ax + (mt * 4 + kt) * 128;
#pragma unroll
        for (int j = 0; j < 4; j++)
            base[((slotb + j) ^ kt) * 4 + reg] = vv[j];
    }
    // stage w1[128][32] in B-frag order
#pragma unroll
    for (int i = 0; i < 4; i++) {
        int q = tid + i * 256;
        int n = q >> 3, k4 = (q & 7) * 4;
        float4 v = *reinterpret_cast<const float4*>(&w1[(size_t)n * C + k4]);
        float vv[4] = { tf32r(v.x), tf32r(v.y), tf32r(v.z), tf32r(v.w) };
        int nt = n >> 3, rr = n & 7;
        int kt = k4 >> 3, reg = (k4 & 7) >> 2;
        int slotb = rr * 4;
        float* base = Bw1 + (nt * 4 + kt) * 64;
#pragma unroll
        for (int j = 0; j < 4; j++)
            base[((slotb + j) ^ kt) * 2 + reg] = vv[j];
    }
    __syncthreads();

    for (int pass = 0; pass < 2; pass++) {
        float d[2][8][4] = {};
#pragma unroll
        for (int kt = 0; kt < 4; kt++) {
            int lp = lane ^ kt;
            uint32_t a[2][4], b[8][2];
#pragma unroll
            for (int mi = 0; mi < 2; mi++) {
                int mt = warp * 2 + mi;
                *reinterpret_cast<float4*>(a[mi]) =
                    *reinterpret_cast<const float4*>(&Ax[(mt * 4 + kt) * 128 + lp * 4]);
            }
#pragma unroll
            for (int ni = 0; ni < 8; ni++) {
                int nt = pass * 8 + ni;
                *reinterpret_cast<float2*>(b[ni]) =
                    *reinterpret_cast<const float2*>(&Bw1[(nt * 4 + kt) * 64 + lp * 2]);
            }
#pragma unroll
            for (int mi = 0; mi < 2; mi++)
#pragma unroll
                for (int ni = 0; ni < 8; ni++)
                    mma8(d[mi][ni], a[mi], b[ni]);
        }
        // stats over this warp's 32 rows
#pragma unroll
        for (int ni = 0; ni < 8; ni++) {
#pragma unroll
            for (int par = 0; par < 2; par++) {
                int chp = ni * 8 + tig * 2 + par;
                float bias = sb1[pass * 64 + chp];
                float s = 0.f, qq = 0.f;
#pragma unroll
                for (int mi = 0; mi < 2; mi++) {
                    float v0 = d[mi][ni][par] + bias;
                    float v1 = d[mi][ni][par + 2] + bias;
                    s += v0 + v1;
                    qq = fmaf(v0, v0, qq); qq = fmaf(v1, v1, qq);
                }
#pragma unroll
                for (int o = 4; o < 32; o <<= 1) {
                    s  += __shfl_xor_sync(0xFFFFFFFFu, s, o);
                    qq += __shfl_xor_sync(0xFFFFFFFFu, qq, o);
                }
                if (gid == 0) { ps[warp * 64 + chp] = s; pq[warp * 64 + chp] = qq; }
            }
        }
        __syncthreads();
        if (tid < 64) {
            float s = 0.f, qq = 0.f;
#pragma unroll
            for (int w = 0; w < 8; w++) { s += ps[w * 64 + tid]; qq += pq[w * 64 + tid]; }
            g_p1s[blockIdx.x * K1C + pass * 64 + tid] = s;
            g_p1q[blockIdx.x * K1C + pass * 64 + tid] = qq;
        }
        __syncthreads();
    }
}

// ---------------- BN finalize ----------------
__global__ void k_fin1(const float* __restrict__ g, const float* __restrict__ be,
                       int nblk, float invN) {
    const int ch = blockIdx.x;
    __shared__ float rs[256], rq[256];
    float s = 0.f, q = 0.f;
    for (int i = threadIdx.x; i < nblk; i += 256) {
        s += g_p1s[i * K1C + ch]; q += g_p1q[i * K1C + ch];
    }
    rs[threadIdx.x] = s; rq[threadIdx.x] = q; __syncthreads();
    for (int o = 128; o > 0; o >>= 1) {
        if (threadIdx.x < o) { rs[threadIdx.x] += rs[threadIdx.x + o]; rq[threadIdx.x] += rq[threadIdx.x + o]; }
        __syncthreads();
    }
    if (threadIdx.x == 0) {
        float mu = rs[0] * invN, var = rq[0] * invN - mu * mu;
        float a = g[ch] * rsqrtf(var + EPS_BN);
        g_a1[ch] = a; g_bb1[ch] = be[ch] - mu * a;
    }
}
__global__ void k_fin2(const float* __restrict__ g, const float* __restrict__ be,
                       int nblk, float invN) {
    const int ch = blockIdx.x;
    __shared__ float rs[256], rq[256];
    float s = 0.f, q = 0.f;
    const float* ps = g_p2s + (size_t)ch * nblk;
    const float* pq = g_p2q + (size_t)ch * nblk;
    for (int i = threadIdx.x; i < nblk; i += 256) { s += ps[i]; q += pq[i]; }
    rs[threadIdx.x] = s; rq[threadIdx.x] = q; __syncthreads();
    for (int o = 128; o > 0; o >>= 1) {
        if (threadIdx.x < o) { rs[threadIdx.x] += rs[threadIdx.x + o]; rq[threadIdx.x] += rq[threadIdx.x + o]; }
        __syncthreads();
    }
    if (threadIdx.x == 0) {
        float mu = rs[0] * invN, var = rq[0] * invN - mu * mu;
        float a = g[ch] * rsqrtf(var + EPS_BN);
        g_a2[ch] = a; g_bb2[ch] = be[ch] - mu * a;
    }
}

// ======= GEMM2: h recomputed in-prologue via tf32 MMA, then 8 N-passes =====
// smem floats: As 16384 | Bs 8192 (prologue: Ax 4096 | Bw1 4096) | sA1 128 |
// sB1p 128 | sb2 512 | ps 256 | pq 256 = 25856
constexpr int G2_OFF_BS = 16384, G2_OFF_SA1 = 24576, G2_OFF_SB1P = 24704;
constexpr int G2_OFF_SB2 = 24832, G2_OFF_PS = 25344, G2_OFF_PQ = 25600;
constexpr int G2_SMEM_FLOATS = 25856;

__global__ void __launch_bounds__(256, 2) k_gemm2(const float* __restrict__ x,
                                                  const float* __restrict__ w1,
                                                  const float* __restrict__ b1,
                                                  const float* __restrict__ w2,
                                                  const float* __restrict__ b2,
                                                  int Np, int nblk) {
    extern __shared__ float sm[];
    float* As   = sm;
    float* Bs   = sm + G2_OFF_BS;
    float* Ax   = Bs;                  // prologue aliases
    float* Bw1  = Bs + 4096;
    float* sA1  = sm + G2_OFF_SA1;
    float* sB1p = sm + G2_OFF_SB1P;
    float* sb2  = sm + G2_OFF_SB2;
    float* ps   = sm + G2_OFF_PS;
    float* pq   = sm + G2_OFF_PQ;
    const int tid = threadIdx.x, lane = tid & 31, warp = tid >> 5;
    const int wm = warp >> 1, wn = warp & 1;
    const int gid = lane >> 2, tig = lane & 3;
    const int row0 = blockIdx.x * 128;

    if (tid < 128) {
        float a1 = g_a1[tid];
        sA1[tid]  = a1;
        sB1p[tid] = fmaf(a1, __ldg(&b1[tid]), g_bb1[tid]);
    }
    sb2[tid] = __ldg(&b2[tid]); sb2[tid + 256] = __ldg(&b2[tid + 256]);

    // ---- prologue: recompute h tile = x[128,32] @ w1^T via MMA ----
#pragma unroll
    for (int i = 0; i < 4; i++) {
        int q = tid + i * 256;
        int r = q >> 3, k4 = (q & 7) * 4;
        float4 v = *reinterpret_cast<const float4*>(&x[(size_t)(row0 + r) * C + k4]);
        float vv[4] = { tf32r(v.x), tf32r(v.y), tf32r(v.z), tf32r(v.w) };
        int mt = r >> 4, rr = r & 15;
        int kt = k4 >> 3, reg = (rr >> 3) + ((k4 & 7) >> 2) * 2;
        int slotb = (rr & 7) * 4;
        float* base = Ax + (mt * 4 + kt) * 128;
#pragma unroll
        for (int j = 0; j < 4; j++)
            base[((slotb + j) ^ kt) * 4 + reg] = vv[j];
    }
#pragma unroll
    for (int i = 0; i < 4; i++) {
        int q = tid + i * 256;
        int n = q >> 3, k4 = (q & 7) * 4;
        float4 v = *reinterpret_cast<const float4*>(&w1[(size_t)n * C + k4]);
        float vv[4] = { tf32r(v.x), tf32r(v.y), tf32r(v.z), tf32r(v.w) };
        int nt = n >> 3, rr = n & 7;
        int kt = k4 >> 3, reg = (k4 & 7) >> 2;
        int slotb = rr * 4;
        float* base = Bw1 + (nt * 4 + kt) * 64;
#pragma unroll
        for (int j = 0; j < 4; j++)
            base[((slotb + j) ^ kt) * 2 + reg] = vv[j];
    }
    __syncthreads();

    {
        float d1[2][8][4] = {};
#pragma unroll
        for (int kt = 0; kt < 4; kt++) {
            int lp = lane ^ kt;
            uint32_t a[2][4], b[8][2];
#pragma unroll
            for (int mi = 0; mi < 2; mi++) {
                int mt = wm * 2 + mi;
                *reinterpret_cast<float4*>(a[mi]) =
                    *reinterpret_cast<const float4*>(&Ax[(mt * 4 + kt) * 128 + lp * 4]);
            }
#pragma unroll
            for (int ni = 0; ni < 8; ni++) {
                int nt = wn * 8 + ni;
                *reinterpret_cast<float2*>(b[ni]) =
                    *reinterpret_cast<const float2*>(&Bw1[(nt * 4 + kt) * 64 + lp * 2]);
            }
#pragma unroll
            for (int mi = 0; mi < 2; mi++)
#pragma unroll
                for (int ni = 0; ni < 8; ni++)
                    mma8(d1[mi][ni], a[mi], b[ni]);
        }
        // h = tf32(relu(aff1(h_pre))) -> As in main-loop fragment layout
#pragma unroll
        for (int mi = 0; mi < 2; mi++)
#pragma unroll
            for (int ni = 0; ni < 8; ni++)
#pragma unroll
                for (int e = 0; e < 4; e++) {
                    int rL = wm * 32 + mi * 16 + gid + 8 * (e >> 1);
                    int kL = wn * 64 + ni * 8 + tig * 2 + (e & 1);
                    float v = tf32r(fmaxf(fmaf(sA1[kL], d1[mi][ni][e], sB1p[kL]), 0.f));
                    int mt = rL >> 4, rr = rL & 15;
                    int kt = kL >> 3;
                    int reg = (rr >> 3) + ((kL & 7) >> 2) * 2;
                    int slot = (((rr & 7) * 4 + (kL & 3)) ^ (kt & 7));
                    As[(mt * 16 + kt) * 128 + slot * 4 + reg] = v;
                }
    }
    __syncthreads();

    // ---- main loop: 8 N-passes of 64 ----
    for (int pass = 0; pass < 8; pass++) {
#pragma unroll
        for (int i = 0; i < 8; i++) {
            int q = tid + i * 256;
            int r = q >> 5, k4 = (q & 31) * 4;
            float4 v = *reinterpret_cast<const float4*>(&w2[(size_t)(pass * 64 + r) * K1C + k4]);
            float vv[4] = { tf32r(v.x), tf32r(v.y), tf32r(v.z), tf32r(v.w) };
            int nt = r >> 3, rr = r & 7;
            int kt = k4 >> 3, reg = (k4 & 7) >> 2;
            int slotb = rr * 4;
            float* base = Bs + (nt * 16 + kt) * 64;
#pragma unroll
            for (int j = 0; j < 4; j++)
                base[((slotb + j) ^ (kt & 7)) * 2 + reg] = vv[j];
        }
        __syncthreads();

        float d[2][4][4] = {};
#pragma unroll
        for (int kt = 0; kt < 16; kt++) {
            int lp = lane ^ (kt & 7);
            uint32_t a[2][4], b[4][2];
#pragma unroll
            for (int mi = 0; mi < 2; mi++) {
                int mt = wm * 2 + mi;
                *reinterpret_cast<float4*>(a[mi]) =
                    *reinterpret_cast<const float4*>(&As[(mt * 16 + kt) * 128 + lp * 4]);
            }
#pragma unroll
            for (int ni = 0; ni < 4; ni++) {
                int nt = wn * 4 + ni;
                *reinterpret_cast<float2*>(b[ni]) =
                    *reinterpret_cast<const float2*>(&Bs[(nt * 16 + kt) * 64 + lp * 2]);
            }
#pragma unroll
            for (int mi = 0; mi < 2; mi++)
#pragma unroll
                for (int ni = 0; ni < 4; ni++)
                    mma8(d[mi][ni], a[mi], b[ni]);
        }

        // epilogue: bias, store attT fp16, BN2 partials from fp32 accumulators
#pragma unroll
        for (int ni = 0; ni < 4; ni++) {
#pragma unroll
            for (int par = 0; par < 2; par++) {
                int chp = wn * 32 + ni * 8 + tig * 2 + par;
                int ch = pass * 64 + chp;
                float bias = sb2[ch];
                float s = 0.f, qq = 0.f;
#pragma unroll
                for (int mi = 0; mi < 2; mi++) {
                    float v0 = d[mi][ni][par] + bias;
                    float v1 = d[mi][ni][par + 2] + bias;
                    int ptb = row0 + wm * 32 + mi * 16 + gid;
                    g_att[(size_t)ch * Np + ptb]     = __float2half_rn(v0);
                    g_att[(size_t)ch * Np + ptb + 8] = __float2half_rn(v1);
                    s += v0 + v1;
                    qq = fmaf(v0, v0, qq); qq = fmaf(v1, v1, qq);
                }
#pragma unroll
                for (int o = 4; o < 32; o <<= 1) {
                    s  += __shfl_xor_sync(0xFFFFFFFFu, s, o);
                    qq += __shfl_xor_sync(0xFFFFFFFFu, qq, o);
                }
                if (gid == 0) { ps[wm * 64 + chp] = s; pq[wm * 64 + chp] = qq; }
            }
        }
        __syncthreads();
        if (tid < 64) {
            float s = ps[tid] + ps[64 + tid] + ps[128 + tid] + ps[192 + tid];
            float qq = pq[tid] + pq[64 + tid] + pq[128 + tid] + pq[192 + tid];
            g_p2s[(size_t)(pass * 64 + tid) * nblk + blockIdx.x] = s;
            g_p2q[(size_t)(pass * 64 + tid) * nblk + blockIdx.x] = qq;
        }
        __syncthreads();
    }
}

// ---------------- Pool: cp.async double-buffered, fp16 att, tf32 mma -------
constexpr int P_AS2 = 72;
constexpr int P_XS = 40;
constexpr int P_OFF_XB = 36864;
constexpr int P_OFF_SA2 = P_OFF_XB + 20480;
constexpr int P_SMEM_BYTES = P_OFF_SA2 + 1024;

__global__ void __launch_bounds__(256) k_pool(const float* __restrict__ x,
                                              int Np, int L, int rpc) {
    extern __shared__ char psmc[];
    __half* attb = reinterpret_cast<__half*>(psmc);
    float* xb   = reinterpret_cast<float*>(psmc + P_OFF_XB);
    float* sA2  = reinterpret_cast<float*>(psmc + P_OFF_SA2);
    float* sB2c = sA2 + 128;
    const int tid = threadIdx.x, lane = tid & 31, warp = tid >> 5;
    const int gid = lane >> 2, tig = lane & 3;
    const int ch0 = blockIdx.x * 128;
    const int b = blockIdx.y / SCH, s = blockIdx.y % SCH;
    const int pt0g = b * L + s * rpc;
    const int nc = rpc / 64;
    const uint32_t attb_u = s2u(attb), xb_u = s2u(xb);

    if (tid < 128) { sA2[tid] = g_a2[ch0 + tid]; sB2c[tid] = g_bb2[ch0 + tid]; }
    for (int i = tid; i < 2 * 64 * 8; i += 256) {
        int buf = i / 512, r = (i / 8) % 64, c = i & 7;
        xb[buf * 64 * P_XS + r * P_XS + 32 + c] = (c == 0) ? 1.f : 0.f;
    }

    auto issue = [&](int ck, int buf) {
        const __half* ga = &g_att[(size_t)ch0 * Np + pt0g + ck * 64];
        uint32_t sa = attb_u + buf * (128 * P_AS2 * 2);
#pragma unroll
        for (int i = 0; i < 4; i++) {
            int q = tid + i * 256;
            int r = q >> 3, c = q & 7;
            cpasync16(sa + (uint32_t)(r * P_AS2 * 2 + c * 16), ga + (size_t)r * Np + c * 8);
        }
        const float* gx = &x[(size_t)(pt0g + ck * 64) * C];
        uint32_t sx = xb_u + buf * (64 * P_XS * 4);
#pragma unroll
        for (int i = 0; i < 2; i++) {
            int q = tid + i * 256;
            int r = q >> 3, c = q & 7;
            cpasync16(sx + (uint32_t)(r * P_XS + c * 4) * 4, gx + r * C + c * 4);
        }
    };

    const float cA0 = g_a2[ch0 + warp * 16 + gid],     cB0 = g_bb2[ch0 + warp * 16 + gid];
    const float cA1 = g_a2[ch0 + warp * 16 + gid + 8], cB1 = g_bb2[ch0 + warp * 16 + gid + 8];

    float d[5][4] = {};
    issue(0, 0);
    CP_COMMIT();

    for (int ck = 0; ck < nc; ck++) {
        if (ck + 1 < nc) { issue(ck + 1, (ck + 1) & 1); CP_COMMIT(); CP_WAIT(1); }
        else             { CP_WAIT(0); }
        __syncthreads();

        const __half* ab = attb + (ck & 1) * (128 * P_AS2);
        const float* xv = xb + (ck & 1) * (64 * P_XS);
        const __half* ar0 = ab + (warp * 16 + gid) * P_AS2;
        const __half* ar1 = ar0 + 8 * P_AS2;
#pragma unroll
        for (int kt = 0; kt < 8; kt++) {
            uint32_t a[4];
            a[0] = __float_as_uint(tf32r(fmaxf(fmaf(cA0, __half2float(ar0[kt * 8 + tig]), cB0), 0.f)));
            a[1] = __float_as_uint(tf32r(fmaxf(fmaf(cA1, __half2float(ar1[kt * 8 + tig]), cB1), 0.f)));
            a[2] = __float_as_uint(tf32r(fmaxf(fmaf(cA0, __half2float(ar0[kt * 8 + tig + 4]), cB0), 0.f)));
            a[3] = __float_as_uint(tf32r(fmaxf(fmaf(cA1, __half2float(ar1[kt * 8 + tig + 4]), cB1), 0.f)));
#pragma unroll
            for (int ni = 0; ni < 5; ni++) {
                const float* br = xv + (kt * 8 + tig) * P_XS + ni * 8 + gid;
                uint32_t bb[2];
                bb[0] = __float_as_uint(tf32r(br[0]));
                bb[1] = __float_as_uint(tf32r(br[4 * P_XS]));
                mma8(d[ni], a, bb);
            }
        }
        __syncthreads();
    }

    const int seg = b * SCH + s;
#pragma unroll
    for (int ni = 0; ni < 5; ni++) {
#pragma unroll
        for (int c = 0; c < 4; c++) {
            int n = ni * 8 + tig * 2 + (c & 1);
            int ch = ch0 + warp * 16 + gid + 8 * (c >> 1);
            if (n < 32)
                g_ppool[((size_t)seg * K2C + ch) * C + n] = d[ni][c];
            else if (n == 32)
                g_pgp[(size_t)seg * K2C + ch] = d[ni][c];
        }
    }
}

__global__ void k_poolred(float invL, int B) {
    int idx = blockIdx.x * 256 + threadIdx.x;
    if (idx >= B * K2C * C) return;
    int b = idx / (K2C * C), rem = idx % (K2C * C);
    float s = 0.f;
#pragma unroll
    for (int t = 0; t < SCH; t++) s += g_ppool[(size_t)(b * SCH + t) * (K2C * C) + rem];
    g_pooled[idx] = s * invL;
}
__global__ void k_gpred(float* __restrict__ out, int B, int L) {
    int idx = blockIdx.x * 256 + threadIdx.x;
    if (idx >= B * K2C) return;
    int b = idx / K2C, k = idx % K2C;
    float s = 0.f;
#pragma unroll
    for (int t = 0; t < SCH; t++) s += g_pgp[(size_t)(b * SCH + t) * K2C + k];
    out[(size_t)B * FCC + (size_t)b * K2C + k] = s;
    if (k == 0) out[(size_t)B * (FCC + K2C) + b] = (float)L;
}

// ---------------- final FC + BN + L2 norm ----------------
__global__ void __launch_bounds__(128) k_final(const float* __restrict__ wf,
                                               const float* __restrict__ bf,
                                               const float* __restrict__ gf,
                                               const float* __restrict__ bef, int B) {
    const int f = blockIdx.x, tid = threadIdx.x, nq = (K2C * C) / 4;
    float acc[MAXB];
#pragma unroll
    for (int b = 0; b < MAXB; b++) acc[b] = 0.f;
    const float4* wf4 = reinterpret_cast<const float4*>(wf) + (size_t)f * nq;
    const float4* p4 = reinterpret_cast<const float4*>(g_pooled);
    for (int i = tid; i < nq; i += 128) {
        float4 wv = wf4[i];
        for (int b = 0; b < B; b++) {
            float4 pv = p4[(size_t)b * nq + i];
            acc[b] += wv.x * pv.x + wv.y * pv.y + wv.z * pv.z + wv.w * pv.w;
        }
    }
    __shared__ float red[MAXB * 128];
    for (int b = 0; b < B; b++) red[b * 128 + tid] = acc[b];
    __syncthreads();
    for (int o = 64; o > 0; o >>= 1) {
        if (tid < o)
            for (int b = 0; b < B; b++) red[b * 128 + tid] += red[b * 128 + tid + o];
        __syncthreads();
    }
    __shared__ float sv[MAXB], smu, srstd;
    if (tid < B) sv[tid] = red[tid * 128] + bf[f];
    __syncthreads();
    if (tid == 0) {
        float mu = 0.f;
        for (int b = 0; b < B; b++) mu += sv[b];
        mu /= (float)B;
        float var = 0.f;
        for (int b = 0; b < B; b++) { float dd = sv[b] - mu; var += dd * dd; }
        var /= (float)B;
        smu = mu; srstd = rsqrtf(var + EPS_BN);
    }
    __syncthreads();
    if (tid < B) g_resb[tid * FCC + f] = (sv[tid] - smu) * srstd * gf[f] + bef[f];
}

__global__ void __launch_bounds__(FCC) k_norm(float* __restrict__ out) {
    const int b = blockIdx.x, f = threadIdx.x;
    float v = g_resb[b * FCC + f];
    __shared__ float red[FCC];
    red[f] = v * v; __syncthreads();
    for (int o = FCC / 2; o > 0; o >>= 1) {
        if (f < o) red[f] += red[f + o];
        __syncthreads();
    }
    __shared__ float sinv;
    if (f == 0) sinv = 1.f / fmaxf(sqrtf(red[0]), 1e-12f);
    __syncthreads();
    out[(size_t)b * FCC + f] = v * sinv;
}

// ---------------------------------------------------------------------------
extern "C" void kernel_launch(void* const* d_in, const int* in_sizes, int n_in,
                              void* d_out, int out_size) {
    const float* x   = (const float*)d_in[0];
    const float* w1  = (const float*)d_in[1];
    const float* b1  = (const float*)d_in[2];
    const float* g1  = (const float*)d_in[3];
    const float* be1 = (const float*)d_in[4];
    const float* w2  = (const float*)d_in[5];
    const float* b2  = (const float*)d_in[6];
    const float* g2  = (const float*)d_in[7];
    const float* be2 = (const float*)d_in[8];
    const float* wf  = (const float*)d_in[9];
    const float* bf  = (const float*)d_in[10];
    const float* gf  = (const float*)d_in[11];
    const float* bef = (const float*)d_in[12];
    float* out = (float*)d_out;

    const int N = in_sizes[0] / C;
    const int B = out_size / (FCC + K2C + 1);
    const int L = N / B;
    const int rpc = L / SCH;
    const int nblk2 = N / 128;
    const int s1smem = S1_SMEM_FLOATS * 4;
    const int g2smem = G2_SMEM_FLOATS * 4;

    cudaFuncSetAttribute(k_stat1, cudaFuncAttributeMaxDynamicSharedMemorySize, s1smem);
    cudaFuncSetAttribute(k_gemm2, cudaFuncAttributeMaxDynamicSharedMemorySize, g2smem);
    cudaFuncSetAttribute(k_pool, cudaFuncAttributeMaxDynamicSharedMemorySize, P_SMEM_BYTES);

    k_stat1<<<N / 256, 256, s1smem>>>(x, w1, b1);
    k_fin1<<<K1C, 256>>>(g1, be1, N / 256, 1.f / (float)N);
    k_gemm2<<<nblk2, 256, g2smem>>>(x, w1, b1, w2, b2, N, nblk2);
    k_fin2<<<K2C, 256>>>(g2, be2, nblk2, 1.f / (float)N);
    k_pool<<<dim3(K2C / 128, B * SCH), 256, P_SMEM_BYTES>>>(x, N, L, rpc);
    k_poolred<<<(B * K2C * C + 255) / 256, 256>>>(1.f / (float)L, B);
    k_gpred<<<(B * K2C + 255) / 256, 256>>>(out, B, L);
    k_final<<<FCC, 128>>>(wf, bf, gf, bef, B);
    k_norm<<<B, FCC>>>(out);
}

// round 15
// speedup vs baseline: 2.2877x; 1.1635x over previous
#include <cuda_runtime.h>
#include <cuda_fp16.h>
#include <cstdint>

constexpr int C = 32, K1C = 128, K2C = 512, FCC = 256;
constexpr int MAXN = 524288, MAXB = 16, SCH = 16;
constexpr float EPS_BN = 1e-5f;

__device__ __half g_att[(size_t)K2C * MAXN];          // attT fp16 [512][N]
__device__ __half g_xT [(size_t)33 * MAXN];           // xT fp16 [33][N], row32=ones
__device__ float g_p1s [(MAXN / 256) * K1C];
__device__ float g_p1q [(MAXN / 256) * K1C];
__device__ float g_p2s [(size_t)K2C * (MAXN / 128)];  // [ch][blk]
__device__ float g_p2q [(size_t)K2C * (MAXN / 128)];
__device__ float g_a1[K1C], g_bb1[K1C], g_a2[K2C], g_bb2[K2C];
__device__ float g_ppool[(size_t)MAXB * SCH * K2C * C];
__device__ float g_pgp  [(size_t)MAXB * SCH * K2C];
__device__ float g_pooled[(size_t)MAXB * K2C * C];
__device__ float g_resb [MAXB * FCC];

__device__ __forceinline__ float tf32r(float v) {
    float o; asm("cvt.rna.tf32.f32 %0, %1;" : "=f"(o) : "f"(v)); return o;
}
__device__ __forceinline__ void mma8(float* d, const uint32_t* a, const uint32_t* b) {
    asm volatile(
        "mma.sync.aligned.m16n8k8.row.col.f32.tf32.tf32.f32 "
        "{%0,%1,%2,%3}, {%4,%5,%6,%7}, {%8,%9}, {%0,%1,%2,%3};"
        : "+f"(d[0]), "+f"(d[1]), "+f"(d[2]), "+f"(d[3])
        : "r"(a[0]), "r"(a[1]), "r"(a[2]), "r"(a[3]), "r"(b[0]), "r"(b[1]));
}
__device__ __forceinline__ void mma16(float* d, const uint32_t* a, const uint32_t* b) {
    asm volatile(
        "mma.sync.aligned.m16n8k16.row.col.f32.f16.f16.f32 "
        "{%0,%1,%2,%3}, {%4,%5,%6,%7}, {%8,%9}, {%0,%1,%2,%3};"
        : "+f"(d[0]), "+f"(d[1]), "+f"(d[2]), "+f"(d[3])
        : "r"(a[0]), "r"(a[1]), "r"(a[2]), "r"(a[3]), "r"(b[0]), "r"(b[1]));
}
__device__ __forceinline__ uint32_t s2u(const void* p) {
    uint32_t a;
    asm("{ .reg .u64 t; cvta.to.shared.u64 t, %1; cvt.u32.u64 %0, t; }" : "=r"(a) : "l"(p));
    return a;
}
__device__ __forceinline__ void cpasync16(uint32_t saddr, const void* g) {
    asm volatile("cp.async.cg.shared.global [%0], [%1], 16;" :: "r"(saddr), "l"(g));
}
#define CP_COMMIT() asm volatile("cp.async.commit_group;" ::: "memory")
#define CP_WAIT(n)  asm volatile("cp.async.wait_group %0;" :: "n"(n) : "memory")

__device__ __forceinline__ uint32_t pack2(float lo, float hi) {
    __half2 h = __floats2half2_rn(lo, hi);
    return *reinterpret_cast<uint32_t*>(&h);
}
__device__ __forceinline__ uint32_t affpack(uint32_t raw, float a, float b) {
    __half2 h = *reinterpret_cast<__half2*>(&raw);
    float lo = fmaxf(fmaf(a, __low2float(h), b), 0.f);
    float hi = fmaxf(fmaf(a, __high2float(h), b), 0.f);
    return pack2(lo, hi);
}

// =============== k_xt: x -> fp16 transposed [33][N], row 32 = ones ==========
__global__ void __launch_bounds__(256) k_xt(const float* __restrict__ x, int Np) {
    __shared__ float xs[64 * 33];
    const int tid = threadIdx.x;
    const int pt0 = blockIdx.x * 64;
#pragma unroll
    for (int i = 0; i < 2; i++) {
        int q = tid + i * 256;
        int r = q >> 3, c4 = (q & 7) * 4;
        float4 v = *reinterpret_cast<const float4*>(&x[(size_t)(pt0 + r) * C + c4]);
        xs[r * 33 + c4 + 0] = v.x;
        xs[r * 33 + c4 + 1] = v.y;
        xs[r * 33 + c4 + 2] = v.z;
        xs[r * 33 + c4 + 3] = v.w;
    }
    __syncthreads();
    for (int q = tid; q < 33 * 32; q += 256) {
        int c = q >> 5, p2 = (q & 31) * 2;
        uint32_t u = (c == 32) ? pack2(1.f, 1.f)
                               : pack2(xs[p2 * 33 + c], xs[(p2 + 1) * 33 + c]);
        *reinterpret_cast<uint32_t*>(&g_xT[(size_t)c * Np + pt0 + p2]) = u;
    }
}

// =============== k_stat1: BN1 stats via tf32 MMA ================
constexpr int S1_BW1 = 8192, S1_SB1 = 12288, S1_PS = 12416, S1_PQ = 12928;
constexpr int S1_SMEM_FLOATS = 13440;

__global__ void __launch_bounds__(256, 2) k_stat1(const float* __restrict__ x,
                                                  const float* __restrict__ w1,
                                                  const float* __restrict__ b1) {
    extern __shared__ float sm[];
    float* Ax  = sm;
    float* Bw1 = sm + S1_BW1;
    float* sb1 = sm + S1_SB1;
    float* ps  = sm + S1_PS;
    float* pq  = sm + S1_PQ;
    const int tid = threadIdx.x, lane = tid & 31, warp = tid >> 5;
    const int gid = lane >> 2, tig = lane & 3;
    const int p0 = blockIdx.x * 256;

    if (tid < 128) sb1[tid] = __ldg(&b1[tid]);
#pragma unroll
    for (int i = 0; i < 8; i++) {
        int q = tid + i * 256;
        int r = q >> 3, k4 = (q & 7) * 4;
        float4 v = *reinterpret_cast<const float4*>(&x[(size_t)(p0 + r) * C + k4]);
        float vv[4] = { tf32r(v.x), tf32r(v.y), tf32r(v.z), tf32r(v.w) };
        int mt = r >> 4, rr = r & 15;
        int kt = k4 >> 3, reg = (rr >> 3) + ((k4 & 7) >> 2) * 2;
        int slotb = (rr & 7) * 4;
        float* base = Ax + (mt * 4 + kt) * 128;
#pragma unroll
        for (int j = 0; j < 4; j++)
            base[((slotb + j) ^ kt) * 4 + reg] = vv[j];
    }
#pragma unroll
    for (int i = 0; i < 4; i++) {
        int q = tid + i * 256;
        int n = q >> 3, k4 = (q & 7) * 4;
        float4 v = *reinterpret_cast<const float4*>(&w1[(size_t)n * C + k4]);
        float vv[4] = { tf32r(v.x), tf32r(v.y), tf32r(v.z), tf32r(v.w) };
        int nt = n >> 3, rr = n & 7;
        int kt = k4 >> 3, reg = (k4 & 7) >> 2;
        int slotb = rr * 4;
        float* base = Bw1 + (nt * 4 + kt) * 64;
#pragma unroll
        for (int j = 0; j < 4; j++)
            base[((slotb + j) ^ kt) * 2 + reg] = vv[j];
    }
    __syncthreads();

    for (int pass = 0; pass < 2; pass++) {
        float d[2][8][4] = {};
#pragma unroll
        for (int kt = 0; kt < 4; kt++) {
            int lp = lane ^ kt;
            uint32_t a[2][4], b[8][2];
#pragma unroll
            for (int mi = 0; mi < 2; mi++) {
                int mt = warp * 2 + mi;
                *reinterpret_cast<float4*>(a[mi]) =
                    *reinterpret_cast<const float4*>(&Ax[(mt * 4 + kt) * 128 + lp * 4]);
            }
#pragma unroll
            for (int ni = 0; ni < 8; ni++) {
                int nt = pass * 8 + ni;
                *reinterpret_cast<float2*>(b[ni]) =
                    *reinterpret_cast<const float2*>(&Bw1[(nt * 4 + kt) * 64 + lp * 2]);
            }
#pragma unroll
            for (int mi = 0; mi < 2; mi++)
#pragma unroll
                for (int ni = 0; ni < 8; ni++)
                    mma8(d[mi][ni], a[mi], b[ni]);
        }
#pragma unroll
        for (int ni = 0; ni < 8; ni++) {
#pragma unroll
            for (int par = 0; par < 2; par++) {
                int chp = ni * 8 + tig * 2 + par;
                float bias = sb1[pass * 64 + chp];
                float s = 0.f, qq = 0.f;
#pragma unroll
                for (int mi = 0; mi < 2; mi++) {
                    float v0 = d[mi][ni][par] + bias;
                    float v1 = d[mi][ni][par + 2] + bias;
                    s += v0 + v1;
                    qq = fmaf(v0, v0, qq); qq = fmaf(v1, v1, qq);
                }
#pragma unroll
                for (int o = 4; o < 32; o <<= 1) {
                    s  += __shfl_xor_sync(0xFFFFFFFFu, s, o);
                    qq += __shfl_xor_sync(0xFFFFFFFFu, qq, o);
                }
                if (gid == 0) { ps[warp * 64 + chp] = s; pq[warp * 64 + chp] = qq; }
            }
        }
        __syncthreads();
        if (tid < 64) {
            float s = 0.f, qq = 0.f;
#pragma unroll
            for (int w = 0; w < 8; w++) { s += ps[w * 64 + tid]; qq += pq[w * 64 + tid]; }
            g_p1s[blockIdx.x * K1C + pass * 64 + tid] = s;
            g_p1q[blockIdx.x * K1C + pass * 64 + tid] = qq;
        }
        __syncthreads();
    }
}

// ---------------- BN finalize ----------------
__global__ void k_fin1(const float* __restrict__ g, const float* __restrict__ be,
                       int nblk, float invN) {
    const int ch = blockIdx.x;
    __shared__ float rs[256], rq[256];
    float s = 0.f, q = 0.f;
    for (int i = threadIdx.x; i < nblk; i += 256) {
        s += g_p1s[i * K1C + ch]; q += g_p1q[i * K1C + ch];
    }
    rs[threadIdx.x] = s; rq[threadIdx.x] = q; __syncthreads();
    for (int o = 128; o > 0; o >>= 1) {
        if (threadIdx.x < o) { rs[threadIdx.x] += rs[threadIdx.x + o]; rq[threadIdx.x] += rq[threadIdx.x + o]; }
        __syncthreads();
    }
    if (threadIdx.x == 0) {
        float mu = rs[0] * invN, var = rq[0] * invN - mu * mu;
        float a = g[ch] * rsqrtf(var + EPS_BN);
        g_a1[ch] = a; g_bb1[ch] = be[ch] - mu * a;
    }
}
__global__ void k_fin2(const float* __restrict__ g, const float* __restrict__ be,
                       int nblk, float invN) {
    const int ch = blockIdx.x;
    __shared__ float rs[256], rq[256];
    float s = 0.f, q = 0.f;
    const float* ps = g_p2s + (size_t)ch * nblk;
    const float* pq = g_p2q + (size_t)ch * nblk;
    for (int i = threadIdx.x; i < nblk; i += 256) { s += ps[i]; q += pq[i]; }
    rs[threadIdx.x] = s; rq[threadIdx.x] = q; __syncthreads();
    for (int o = 128; o > 0; o >>= 1) {
        if (threadIdx.x < o) { rs[threadIdx.x] += rs[threadIdx.x + o]; rq[threadIdx.x] += rq[threadIdx.x + o]; }
        __syncthreads();
    }
    if (threadIdx.x == 0) {
        float mu = rs[0] * invN, var = rq[0] * invN - mu * mu;
        float a = g[ch] * rsqrtf(var + EPS_BN);
        g_a2[ch] = a; g_bb2[ch] = be[ch] - mu * a;
    }
}

// ======= GEMM2: fp16 m16n8k16 mainloop, tf32 prologue h-recompute ==========
constexpr int G2_SMEM_U32 = 13568;

__global__ void __launch_bounds__(256, 2) k_gemm2(const float* __restrict__ x,
                                                  const float* __restrict__ w1,
                                                  const float* __restrict__ b1,
                                                  const float* __restrict__ w2,
                                                  const float* __restrict__ b2,
                                                  int Np, int nblk) {
    extern __shared__ float sm[];
    uint32_t* As32 = reinterpret_cast<uint32_t*>(sm);
    uint32_t* Bs32 = reinterpret_cast<uint32_t*>(sm) + 8192;
    float* Ax   = sm;                  // prologue alias (4096 floats)
    float* Bw1  = sm + 4096;           // prologue alias (4096 floats)
    float* sA1  = sm + 12288;
    float* sB1p = sm + 12416;
    float* sb2  = sm + 12544;
    float* ps   = sm + 13056;
    float* pq   = sm + 13312;
    const int tid = threadIdx.x, lane = tid & 31, warp = tid >> 5;
    const int wm = warp >> 1, wn = warp & 1;
    const int gid = lane >> 2, tig = lane & 3;
    const int row0 = blockIdx.x * 128;

    if (tid < 128) {
        float a1 = g_a1[tid];
        sA1[tid]  = a1;
        sB1p[tid] = fmaf(a1, __ldg(&b1[tid]), g_bb1[tid]);
    }
    sb2[tid] = __ldg(&b2[tid]); sb2[tid + 256] = __ldg(&b2[tid + 256]);

    // ---- prologue staging: x[128,32] (FIX: 4 iterations = 1024 float4s) ----
#pragma unroll
    for (int i = 0; i < 4; i++) {
        int q = tid + i * 256;
        int r = q >> 3, k4 = (q & 7) * 4;
        float4 v = *reinterpret_cast<const float4*>(&x[(size_t)(row0 + r) * C + k4]);
        float vv[4] = { tf32r(v.x), tf32r(v.y), tf32r(v.z), tf32r(v.w) };
        int mt = r >> 4, rr = r & 15;
        int kt = k4 >> 3, reg = (rr >> 3) + ((k4 & 7) >> 2) * 2;
        int slotb = (rr & 7) * 4;
        float* base = Ax + (mt * 4 + kt) * 128;
#pragma unroll
        for (int j = 0; j < 4; j++)
            base[((slotb + j) ^ kt) * 4 + reg] = vv[j];
    }
#pragma unroll
    for (int i = 0; i < 4; i++) {
        int q = tid + i * 256;
        int n = q >> 3, k4 = (q & 7) * 4;
        float4 v = *reinterpret_cast<const float4*>(&w1[(size_t)n * C + k4]);
        float vv[4] = { tf32r(v.x), tf32r(v.y), tf32r(v.z), tf32r(v.w) };
        int nt = n >> 3, rr = n & 7;
        int kt = k4 >> 3, reg = (k4 & 7) >> 2;
        int slotb = rr * 4;
        float* base = Bw1 + (nt * 4 + kt) * 64;
#pragma unroll
        for (int j = 0; j < 4; j++)
            base[((slotb + j) ^ kt) * 2 + reg] = vv[j];
    }
    __syncthreads();

    {
        float d1[2][8][4] = {};
#pragma unroll
        for (int kt = 0; kt < 4; kt++) {
            int lp = lane ^ kt;
            uint32_t a[2][4], b[8][2];
#pragma unroll
            for (int mi = 0; mi < 2; mi++) {
                int mt = wm * 2 + mi;
                *reinterpret_cast<float4*>(a[mi]) =
                    *reinterpret_cast<const float4*>(&Ax[(mt * 4 + kt) * 128 + lp * 4]);
            }
#pragma unroll
            for (int ni = 0; ni < 8; ni++) {
                int nt = wn * 8 + ni;
                *reinterpret_cast<float2*>(b[ni]) =
                    *reinterpret_cast<const float2*>(&Bw1[(nt * 4 + kt) * 64 + lp * 2]);
            }
#pragma unroll
            for (int mi = 0; mi < 2; mi++)
#pragma unroll
                for (int ni = 0; ni < 8; ni++)
                    mma8(d1[mi][ni], a[mi], b[ni]);
        }
        __syncthreads();   // prologue frag reads done; As32 (aliased) writable

        // h = fp16(relu(aff1(h_pre))) -> As32 in f16 m16n8k16 fragment layout
#pragma unroll
        for (int mi = 0; mi < 2; mi++)
#pragma unroll
            for (int ni = 0; ni < 8; ni++) {
                int r0 = wm * 32 + mi * 16 + gid;
                int kb = wn * 64 + ni * 8 + tig * 2;
                float a0 = sA1[kb], a1 = sA1[kb + 1];
                float c0 = sB1p[kb], c1 = sB1p[kb + 1];
                float v0 = fmaxf(fmaf(a0, d1[mi][ni][0], c0), 0.f);
                float v1 = fmaxf(fmaf(a1, d1[mi][ni][1], c1), 0.f);
                float v2 = fmaxf(fmaf(a0, d1[mi][ni][2], c0), 0.f);
                float v3 = fmaxf(fmaf(a1, d1[mi][ni][3], c1), 0.f);
#pragma unroll
                for (int h = 0; h < 2; h++) {
                    int r = r0 + 8 * h;
                    int mt = r >> 4, kt2 = kb >> 4;
                    int reg = ((r >> 3) & 1) + (((kb >> 3) & 1) << 1);
                    int sl = ((r & 7) << 2) + ((kb & 7) >> 1);
                    As32[(mt * 8 + kt2) * 128 + sl * 4 + reg] =
                        h ? pack2(v2, v3) : pack2(v0, v1);
                }
            }
    }
    __syncthreads();

    // ---- main loop: 8 N-passes of 64, fp16 k16 MMA ----
    for (int pass = 0; pass < 8; pass++) {
#pragma unroll
        for (int i = 0; i < 8; i++) {
            int q = tid + i * 256;
            int r = q >> 5, k4 = (q & 31) * 4;
            float4 v = *reinterpret_cast<const float4*>(&w2[(size_t)(pass * 64 + r) * K1C + k4]);
            int nt = r >> 3;
            int slbase = ((r & 7) << 2);
#pragma unroll
            for (int half = 0; half < 2; half++) {
                int k = k4 + half * 2;
                int kt2 = k >> 4;
                int reg = (k >> 3) & 1;
                int sl = slbase + ((k & 7) >> 1);
                Bs32[(nt * 8 + kt2) * 64 + sl * 2 + reg] =
                    half ? pack2(v.z, v.w) : pack2(v.x, v.y);
            }
        }
        __syncthreads();

        float d[2][4][4] = {};
#pragma unroll
        for (int kt2 = 0; kt2 < 8; kt2++) {
            uint32_t a[2][4], b[4][2];
#pragma unroll
            for (int mi = 0; mi < 2; mi++)
                *reinterpret_cast<uint4*>(a[mi]) =
                    *reinterpret_cast<const uint4*>(&As32[((wm * 2 + mi) * 8 + kt2) * 128 + lane * 4]);
#pragma unroll
            for (int ni = 0; ni < 4; ni++)
                *reinterpret_cast<uint2*>(b[ni]) =
                    *reinterpret_cast<const uint2*>(&Bs32[((wn * 4 + ni) * 8 + kt2) * 64 + lane * 2]);
#pragma unroll
            for (int mi = 0; mi < 2; mi++)
#pragma unroll
                for (int ni = 0; ni < 4; ni++)
                    mma16(d[mi][ni], a[mi], b[ni]);
        }

        // epilogue: bias, store attT fp16, BN2 partials from fp32 accumulators
#pragma unroll
        for (int ni = 0; ni < 4; ni++) {
#pragma unroll
            for (int par = 0; par < 2; par++) {
                int chp = wn * 32 + ni * 8 + tig * 2 + par;
                int ch = pass * 64 + chp;
                float bias = sb2[ch];
                float s = 0.f, qq = 0.f;
#pragma unroll
                for (int mi = 0; mi < 2; mi++) {
                    float v0 = d[mi][ni][par] + bias;
                    float v1 = d[mi][ni][par + 2] + bias;
                    int ptb = row0 + wm * 32 + mi * 16 + gid;
                    g_att[(size_t)ch * Np + ptb]     = __float2half_rn(v0);
                    g_att[(size_t)ch * Np + ptb + 8] = __float2half_rn(v1);
                    s += v0 + v1;
                    qq = fmaf(v0, v0, qq); qq = fmaf(v1, v1, qq);
                }
#pragma unroll
                for (int o = 4; o < 32; o <<= 1) {
                    s  += __shfl_xor_sync(0xFFFFFFFFu, s, o);
                    qq += __shfl_xor_sync(0xFFFFFFFFu, qq, o);
                }
                if (gid == 0) { ps[wm * 64 + chp] = s; pq[wm * 64 + chp] = qq; }
            }
        }
        __syncthreads();
        if (tid < 64) {
            float s = ps[tid] + ps[64 + tid] + ps[128 + tid] + ps[192 + tid];
            float qq = pq[tid] + pq[64 + tid] + pq[128 + tid] + pq[192 + tid];
            g_p2s[(size_t)(pass * 64 + tid) * nblk + blockIdx.x] = s;
            g_p2q[(size_t)(pass * 64 + tid) * nblk + blockIdx.x] = qq;
        }
        __syncthreads();
    }
}

// ======= Pool: fp16 m16n8k16, cp.async att + xT, ones row -> gp ============
constexpr int PA_STR = 72;                      // halves per att row
constexpr int PX_STR = 72;                      // halves per xT row
constexpr int P_OFF_XTS = 2 * 128 * PA_STR * 2; // 36864
constexpr int P_SMEM_BYTES = P_OFF_XTS + 2 * 40 * PX_STR * 2; // 48384

__global__ void __launch_bounds__(256, 2) k_pool(int Np, int L, int rpc) {
    extern __shared__ char psmc[];
    __half* attb = reinterpret_cast<__half*>(psmc);
    __half* xts  = reinterpret_cast<__half*>(psmc + P_OFF_XTS);
    const int tid = threadIdx.x, lane = tid & 31, warp = tid >> 5;
    const int gid = lane >> 2, tig = lane & 3;
    const int ch0 = blockIdx.x * 128;
    const int b = blockIdx.y / SCH, s = blockIdx.y % SCH;
    const int pt0g = b * L + s * rpc;
    const int nc = rpc / 64;
    const uint32_t attb_u = s2u(attb), xts_u = s2u(xts);

    // zero xT smem rows 33..39 (both buffers) — never overwritten by cp.async
    for (int i = tid; i < 2 * 7 * (PX_STR / 2); i += 256) {
        int buf = i / (7 * 36), rem = i % (7 * 36);
        int r = 33 + rem / 36, c = rem % 36;
        reinterpret_cast<uint32_t*>(xts)[(buf * 40 + r) * 36 + c] = 0;
    }

    auto issue = [&](int ck, int buf) {
        const __half* ga = &g_att[(size_t)ch0 * Np + pt0g + ck * 64];
        uint32_t sa = attb_u + buf * (128 * PA_STR * 2);
#pragma unroll
        for (int i = 0; i < 4; i++) {
            int q = tid + i * 256;
            int r = q >> 3, c = q & 7;
            cpasync16(sa + (uint32_t)(r * PA_STR * 2 + c * 16), ga + (size_t)r * Np + c * 8);
        }
        const __half* gx = &g_xT[pt0g + ck * 64];
        uint32_t sx = xts_u + buf * (40 * PX_STR * 2);
#pragma unroll
        for (int i = 0; i < 2; i++) {
            int q = tid + i * 256;
            if (q < 264) {
                int r = q >> 3, c = q & 7;
                cpasync16(sx + (uint32_t)(r * PX_STR * 2 + c * 16), gx + (size_t)r * Np + c * 8);
            }
        }
    };

    const float cA0 = g_a2[ch0 + warp * 16 + gid],     cB0 = g_bb2[ch0 + warp * 16 + gid];
    const float cA1 = g_a2[ch0 + warp * 16 + gid + 8], cB1 = g_bb2[ch0 + warp * 16 + gid + 8];

    float d[5][4] = {};
    issue(0, 0);
    CP_COMMIT();

    for (int ck = 0; ck < nc; ck++) {
        if (ck + 1 < nc) { issue(ck + 1, (ck + 1) & 1); CP_COMMIT(); CP_WAIT(1); }
        else             { CP_WAIT(0); }
        __syncthreads();

        const int buf = ck & 1;
        const __half* ar0 = attb + buf * (128 * PA_STR) + (warp * 16 + gid) * PA_STR;
        const __half* ar1 = ar0 + 8 * PA_STR;
        const __half* xr  = xts + buf * (40 * PX_STR);
#pragma unroll
        for (int kt2 = 0; kt2 < 4; kt2++) {
            uint32_t a[4];
            a[0] = affpack(*reinterpret_cast<const uint32_t*>(ar0 + kt2 * 16 + tig * 2), cA0, cB0);
            a[1] = affpack(*reinterpret_cast<const uint32_t*>(ar1 + kt2 * 16 + tig * 2), cA1, cB1);
            a[2] = affpack(*reinterpret_cast<const uint32_t*>(ar0 + kt2 * 16 + tig * 2 + 8), cA0, cB0);
            a[3] = affpack(*reinterpret_cast<const uint32_t*>(ar1 + kt2 * 16 + tig * 2 + 8), cA1, cB1);
#pragma unroll
            for (int ni = 0; ni < 5; ni++) {
                const __half* bp = xr + (ni * 8 + gid) * PX_STR + kt2 * 16 + tig * 2;
                uint32_t bb[2];
                bb[0] = *reinterpret_cast<const uint32_t*>(bp);
                bb[1] = *reinterpret_cast<const uint32_t*>(bp + 8);
                mma16(d[ni], a, bb);
            }
        }
        __syncthreads();
    }

    const int seg = b * SCH + s;
#pragma unroll
    for (int ni = 0; ni < 5; ni++) {
#pragma unroll
        for (int c = 0; c < 4; c++) {
            int n = ni * 8 + tig * 2 + (c & 1);
            int ch = ch0 + warp * 16 + gid + 8 * (c >> 1);
            if (n < 32)
                g_ppool[((size_t)seg * K2C + ch) * C + n] = d[ni][c];
            else if (n == 32)
                g_pgp[(size_t)seg * K2C + ch] = d[ni][c];
        }
    }
}

__global__ void k_poolred(float invL, int B) {
    int idx = blockIdx.x * 256 + threadIdx.x;
    if (idx >= B * K2C * C) return;
    int b = idx / (K2C * C), rem = idx % (K2C * C);
    float s = 0.f;
#pragma unroll
    for (int t = 0; t < SCH; t++) s += g_ppool[(size_t)(b * SCH + t) * (K2C * C) + rem];
    g_pooled[idx] = s * invL;
}
__global__ void k_gpred(float* __restrict__ out, int B, int L) {
    int idx = blockIdx.x * 256 + threadIdx.x;
    if (idx >= B * K2C) return;
    int b = idx / K2C, k = idx % K2C;
    float s = 0.f;
#pragma unroll
    for (int t = 0; t < SCH; t++) s += g_pgp[(size_t)(b * SCH + t) * K2C + k];
    out[(size_t)B * FCC + (size_t)b * K2C + k] = s;
    if (k == 0) out[(size_t)B * (FCC + K2C) + b] = (float)L;
}

// ---------------- final FC + BN + L2 norm ----------------
__global__ void __launch_bounds__(128) k_final(const float* __restrict__ wf,
                                               const float* __restrict__ bf,
                                               const float* __restrict__ gf,
                                               const float* __restrict__ bef, int B) {
    const int f = blockIdx.x, tid = threadIdx.x, nq = (K2C * C) / 4;
    float acc[MAXB];
#pragma unroll
    for (int b = 0; b < MAXB; b++) acc[b] = 0.f;
    const float4* wf4 = reinterpret_cast<const float4*>(wf) + (size_t)f * nq;
    const float4* p4 = reinterpret_cast<const float4*>(g_pooled);
    for (int i = tid; i < nq; i += 128) {
        float4 wv = wf4[i];
        for (int b = 0; b < B; b++) {
            float4 pv = p4[(size_t)b * nq + i];
            acc[b] += wv.x * pv.x + wv.y * pv.y + wv.z * pv.z + wv.w * pv.w;
        }
    }
    __shared__ float red[MAXB * 128];
    for (int b = 0; b < B; b++) red[b * 128 + tid] = acc[b];
    __syncthreads();
    for (int o = 64; o > 0; o >>= 1) {
        if (tid < o)
            for (int b = 0; b < B; b++) red[b * 128 + tid] += red[b * 128 + tid + o];
        __syncthreads();
    }
    __shared__ float sv[MAXB], smu, srstd;
    if (tid < B) sv[tid] = red[tid * 128] + bf[f];
    __syncthreads();
    if (tid == 0) {
        float mu = 0.f;
        for (int b = 0; b < B; b++) mu += sv[b];
        mu /= (float)B;
        float var = 0.f;
        for (int b = 0; b < B; b++) { float dd = sv[b] - mu; var += dd * dd; }
        var /= (float)B;
        smu = mu; srstd = rsqrtf(var + EPS_BN);
    }
    __syncthreads();
    if (tid < B) g_resb[tid * FCC + f] = (sv[tid] - smu) * srstd * gf[f] + bef[f];
}

__global__ void __launch_bounds__(FCC) k_norm(float* __restrict__ out) {
    const int b = blockIdx.x, f = threadIdx.x;
    float v = g_resb[b * FCC + f];
    __shared__ float red[FCC];
    red[f] = v * v; __syncthreads();
    for (int o = FCC / 2; o > 0; o >>= 1) {
        if (f < o) red[f] += red[f + o];
        __syncthreads();
    }
    __shared__ float sinv;
    if (f == 0) sinv = 1.f / fmaxf(sqrtf(red[0]), 1e-12f);
    __syncthreads();
    out[(size_t)b * FCC + f] = v * sinv;
}

// ---------------------------------------------------------------------------
extern "C" void kernel_launch(void* const* d_in, const int* in_sizes, int n_in,
                              void* d_out, int out_size) {
    const float* x   = (const float*)d_in[0];
    const float* w1  = (const float*)d_in[1];
    const float* b1  = (const float*)d_in[2];
    const float* g1  = (const float*)d_in[3];
    const float* be1 = (const float*)d_in[4];
    const float* w2  = (const float*)d_in[5];
    const float* b2  = (const float*)d_in[6];
    const float* g2  = (const float*)d_in[7];
    const float* be2 = (const float*)d_in[8];
    const float* wf  = (const float*)d_in[9];
    const float* bf  = (const float*)d_in[10];
    const float* gf  = (const float*)d_in[11];
    const float* bef = (const float*)d_in[12];
    float* out = (float*)d_out;

    const int N = in_sizes[0] / C;
    const int B = out_size / (FCC + K2C + 1);
    const int L = N / B;
    const int rpc = L / SCH;
    const int nblk2 = N / 128;
    const int s1smem = S1_SMEM_FLOATS * 4;
    const int g2smem = G2_SMEM_U32 * 4;

    cudaFuncSetAttribute(k_stat1, cudaFuncAttributeMaxDynamicSharedMemorySize, s1smem);
    cudaFuncSetAttribute(k_gemm2, cudaFuncAttributeMaxDynamicSharedMemorySize, g2smem);
    cudaFuncSetAttribute(k_pool, cudaFuncAttributeMaxDynamicSharedMemorySize, P_SMEM_BYTES);

    k_stat1<<<N / 256, 256, s1smem>>>(x, w1, b1);
    k_xt<<<N / 64, 256>>>(x, N);
    k_fin1<<<K1C, 256>>>(g1, be1, N / 256, 1.f / (float)N);
    k_gemm2<<<nblk2, 256, g2smem>>>(x, w1, b1, w2, b2, N, nblk2);
    k_fin2<<<K2C, 256>>>(g2, be2, nblk2, 1.f / (float)N);
    k_pool<<<dim3(K2C / 128, B * SCH), 256, P_SMEM_BYTES>>>(N, L, rpc);
    k_poolred<<<(B * K2C * C + 255) / 256, 256>>>(1.f / (float)L, B);
    k_gpred<<<(B * K2C + 255) / 256, 256>>>(out, B, L);
    k_final<<<FCC, 128>>>(wf, bf, gf, bef, B);
    k_norm<<<B, FCC>>>(out);
}